// round 4
// baseline (speedup 1.0000x reference)
#include <cuda_runtime.h>
#include <cuda_bf16.h>
#include <math.h>

// Problem constants
#define BATCH 2
#define SEQ   2048
#define DIM   768
#define NH    12
#define DH    64
#define ROPE_DIM 60
#define HALF  10

// ---------------- scratch (static device arrays; no allocation) -------------
__device__ float g_qkv[BATCH * SEQ * 3 * DIM];        // [4096][2304]
__device__ float g_q[BATCH * NH * SEQ * DH];          // [b][h][n][d]
__device__ float g_k[BATCH * NH * SEQ * DH];
__device__ float g_v[BATCH * NH * SEQ * DH];
__device__ float g_att[BATCH * SEQ * DIM];            // [b][n][h*DH]

// =====================================================================
// GEMM: C[M][Nn] = A[M][K] * B[Nn][K]^T (+ bias), all row-major fp32
// 128x128 tile, BK=16, 256 threads, 8x8 per thread, scalar FMA.
// (UNCHANGED from Round 3 — control arm of the bisect.)
// =====================================================================
#define GBM 128
#define GBN 128
#define GBK 16
#define GLDA (GBM + 4)

__global__ __launch_bounds__(256, 2)
void gemm_nt_kernel(const float* __restrict__ A, const float* __restrict__ Bw,
                    const float* __restrict__ bias, float* __restrict__ C,
                    int M, int Nn, int K)
{
    __shared__ float As[GBK][GLDA];
    __shared__ float Bs[GBK][GLDA];

    const int tid = threadIdx.x;
    const int tx = tid & 15;
    const int ty = tid >> 4;
    const int mBase = blockIdx.y * GBM;
    const int nBase = blockIdx.x * GBN;

    float acc[8][8];
#pragma unroll
    for (int i = 0; i < 8; ++i)
#pragma unroll
        for (int j = 0; j < 8; ++j) acc[i][j] = 0.0f;

    for (int k0 = 0; k0 < K; k0 += GBK) {
#pragma unroll
        for (int f = 0; f < 2; ++f) {
            int lin = tid + f * 256;
            int r  = lin >> 2;
            int kq = (lin & 3) << 2;
            float4 a = *(const float4*)&A[(size_t)(mBase + r) * K + k0 + kq];
            As[kq + 0][r] = a.x; As[kq + 1][r] = a.y;
            As[kq + 2][r] = a.z; As[kq + 3][r] = a.w;
            float4 b = *(const float4*)&Bw[(size_t)(nBase + r) * K + k0 + kq];
            Bs[kq + 0][r] = b.x; Bs[kq + 1][r] = b.y;
            Bs[kq + 2][r] = b.z; Bs[kq + 3][r] = b.w;
        }
        __syncthreads();

#pragma unroll
        for (int kk = 0; kk < GBK; ++kk) {
            float a[8], b[8];
            *(float4*)&a[0] = *(const float4*)&As[kk][ty * 8];
            *(float4*)&a[4] = *(const float4*)&As[kk][ty * 8 + 4];
            *(float4*)&b[0] = *(const float4*)&Bs[kk][tx * 8];
            *(float4*)&b[4] = *(const float4*)&Bs[kk][tx * 8 + 4];
#pragma unroll
            for (int i = 0; i < 8; ++i)
#pragma unroll
                for (int j = 0; j < 8; ++j)
                    acc[i][j] = fmaf(a[i], b[j], acc[i][j]);
        }
        __syncthreads();
    }

#pragma unroll
    for (int i = 0; i < 8; ++i) {
        int m = mBase + ty * 8 + i;
        float* crow = &C[(size_t)m * Nn + nBase + tx * 8];
#pragma unroll
        for (int jj = 0; jj < 2; ++jj) {
            float4 o;
            o.x = acc[i][jj * 4 + 0];
            o.y = acc[i][jj * 4 + 1];
            o.z = acc[i][jj * 4 + 2];
            o.w = acc[i][jj * 4 + 3];
            if (bias) {
                const float* bb = &bias[nBase + tx * 8 + jj * 4];
                o.x += bb[0]; o.y += bb[1]; o.z += bb[2]; o.w += bb[3];
            }
            *(float4*)&crow[jj * 4] = o;
        }
    }
}

// =====================================================================
// NAIVE rmsnorm + rope + split. One thread per (b,n,h). Fully serial,
// no shuffles, exact libm math. Structurally different from old version.
// =====================================================================
__global__ void naive_norm_rope(const float* __restrict__ pos,
                                const float* __restrict__ qn_w,
                                const float* __restrict__ kn_w)
{
    int idx = blockIdx.x * blockDim.x + threadIdx.x;   // (b*SEQ+n)*NH + h
    if (idx >= BATCH * SEQ * NH) return;
    int h   = idx % NH;
    int tok = idx / NH;                                // b*SEQ + n
    int b = tok / SEQ, n = tok % SEQ;

    const float* row = g_qkv + (size_t)tok * (3 * DIM) + h * DH;
    float q[DH], k[DH], v[DH];
    float sq = 0.f, sk = 0.f;
    for (int d = 0; d < DH; ++d) {
        q[d] = row[d];
        k[d] = row[DIM + d];
        v[d] = row[2 * DIM + d];
        sq += q[d] * q[d];
        sk += k[d] * k[d];
    }
    float rq = rsqrtf(sq / DH + 1e-6f);
    float rk = rsqrtf(sk / DH + 1e-6f);
    for (int d = 0; d < DH; ++d) {
        q[d] *= rq * qn_w[d];
        k[d] *= rk * kn_w[d];
    }

    // rope on first ROPE_DIM dims: pair p -> angle index p = axis*HALF + j
    for (int p = 0; p < ROPE_DIM / 2; ++p) {
        int axis = p / HALF;
        int j = p - axis * HALF;
        float freq = powf(10000.0f, -(float)j / (float)HALF);
        float ang = pos[(size_t)tok * 3 + axis] * freq;
        float c = cosf(ang), s = sinf(ang);
        float qe = q[2*p] * c - q[2*p+1] * s;
        float qo = q[2*p] * s + q[2*p+1] * c;
        q[2*p] = qe; q[2*p+1] = qo;
        float ke = k[2*p] * c - k[2*p+1] * s;
        float ko = k[2*p] * s + k[2*p+1] * c;
        k[2*p] = ke; k[2*p+1] = ko;
    }

    size_t ob = ((size_t)(b * NH + h) * SEQ + n) * DH;
    for (int d = 0; d < DH; ++d) {
        g_q[ob + d] = q[d];
        g_k[ob + d] = k[d];
        g_v[ob + d] = v[d];
    }
}

// =====================================================================
// NAIVE attention. One thread per (b,h,qpos). Serial online softmax over
// all keys. No smem, no cross-thread state, no transposes.
// =====================================================================
__global__ void naive_attn()
{
    int idx = blockIdx.x * blockDim.x + threadIdx.x;   // bh*SEQ + qpos
    if (idx >= BATCH * NH * SEQ) return;
    int qpos = idx % SEQ;
    int bh   = idx / SEQ;
    int b = bh / NH, h = bh % NH;

    const float* Q = g_q + ((size_t)bh * SEQ + qpos) * DH;
    const float* K = g_k + (size_t)bh * SEQ * DH;
    const float* V = g_v + (size_t)bh * SEQ * DH;

    float q[DH];
    for (int d = 0; d < DH; ++d) q[d] = Q[d];

    float m = -INFINITY, l = 0.f;
    float O[DH];
    for (int d = 0; d < DH; ++d) O[d] = 0.f;

    for (int kpos = 0; kpos < SEQ; ++kpos) {
        float s = 0.f;
        const float* Kr = K + (size_t)kpos * DH;
        for (int d = 0; d < DH; ++d) s = fmaf(q[d], Kr[d], s);
        s *= 0.125f;                       // DH^-0.5
        float mn = fmaxf(m, s);
        float alpha = expf(m - mn);        // exp(-inf)=0 on first iter
        float p = expf(s - mn);
        l = l * alpha + p;
        const float* Vr = V + (size_t)kpos * DH;
        for (int d = 0; d < DH; ++d) O[d] = O[d] * alpha + p * Vr[d];
        m = mn;
    }

    float inv = 1.0f / l;
    size_t off = ((size_t)(b * SEQ + qpos) * NH + h) * DH;
    for (int d = 0; d < DH; ++d) g_att[off + d] = O[d] * inv;
}

// =====================================================================
// host launcher
// =====================================================================
extern "C" void kernel_launch(void* const* d_in, const int* in_sizes, int n_in,
                              void* d_out, int out_size)
{
    // Dispatch inputs by element count (robust to metadata ordering).
    const float *x = 0, *pos = 0, *qkv_w = 0, *proj_w = 0, *proj_b = 0;
    const float *qn_w = 0, *kn_w = 0;
    for (int i = 0; i < n_in; ++i) {
        int s = in_sizes[i];
        const float* p = (const float*)d_in[i];
        if      (s == BATCH * SEQ * DIM)  x = p;
        else if (s == BATCH * SEQ * 3)    pos = p;
        else if (s == 3 * DIM * DIM)      qkv_w = p;
        else if (s == DIM * DIM)          proj_w = p;
        else if (s == DIM)                proj_b = p;
        else if (s == DH) { if (!qn_w) qn_w = p; else kn_w = p; }
    }
    float* out = (float*)d_out;

    float *qkv, *att;
    cudaGetSymbolAddress((void**)&qkv, g_qkv);
    cudaGetSymbolAddress((void**)&att, g_att);

    // 1) qkv = x @ qkv_w^T   [4096 x 2304]
    gemm_nt_kernel<<<dim3(3 * DIM / GBN, BATCH * SEQ / GBM), 256>>>(
        x, qkv_w, nullptr, qkv, BATCH * SEQ, 3 * DIM, DIM);

    // 2) naive rmsnorm + rope + split
    {
        int total = BATCH * SEQ * NH;
        naive_norm_rope<<<(total + 127) / 128, 128>>>(pos, qn_w, kn_w);
    }

    // 3) naive attention
    {
        int total = BATCH * NH * SEQ;
        naive_attn<<<(total + 127) / 128, 128>>>();
    }

    // 4) out = att @ proj_w^T + proj_b
    gemm_nt_kernel<<<dim3(DIM / GBN, BATCH * SEQ / GBM), 256>>>(
        att, proj_w, proj_b, out, BATCH * SEQ, DIM, DIM);
}

// round 5
// speedup vs baseline: 2.1023x; 2.1023x over previous
#include <cuda_runtime.h>
#include <cuda_bf16.h>
#include <math.h>

// Problem constants
#define BATCH 2
#define SEQ   2048
#define DIM   768
#define NH    12
#define DH    64
#define ROPE_DIM 60
#define HALF  10

// ---------------- scratch (static device arrays; no allocation) -------------
__device__ float g_qkv[BATCH * SEQ * 3 * DIM];        // [4096][2304]
__device__ float g_q[BATCH * NH * SEQ * DH];          // [b][h][n][d]
__device__ float g_k[BATCH * NH * SEQ * DH];
__device__ float g_v[BATCH * NH * SEQ * DH];
__device__ float g_att[BATCH * SEQ * DIM];            // [b][n][h*DH]

// ---------------- f32x2 packed helpers (sm_100+; exonerated in R3/R4) -------
__device__ __forceinline__ unsigned long long pk2(float x) {
    unsigned long long r;
    asm("mov.b64 %0, {%1, %1};" : "=l"(r) : "r"(__float_as_uint(x)));
    return r;
}
__device__ __forceinline__ void fma2(unsigned long long &d,
                                     unsigned long long a, unsigned long long b) {
    asm("fma.rn.f32x2 %0, %1, %2, %3;" : "=l"(d) : "l"(a), "l"(b), "l"(d));
}
__device__ __forceinline__ void mul2(unsigned long long &d, unsigned long long a) {
    asm("mul.rn.f32x2 %0, %1, %2;" : "=l"(d) : "l"(d), "l"(a));
}
__device__ __forceinline__ float lo32(unsigned long long v) {
    return __uint_as_float((unsigned)(v & 0xffffffffULL));
}
__device__ __forceinline__ float hi32(unsigned long long v) {
    return __uint_as_float((unsigned)(v >> 32));
}

// =====================================================================
// GEMM: C[M][Nn] = A[M][K] * B[Nn][K]^T (+ bias), row-major fp32.
// 128x128 tile, BK=16, 256 threads, 8x8/thread, f32x2 FMA.
// (R2 variant — output-identical to the R3 scalar version proven in R4.)
// =====================================================================
#define GBM 128
#define GBN 128
#define GBK 16
#define GLDA (GBM + 4)

__global__ __launch_bounds__(256, 2)
void gemm_nt_kernel(const float* __restrict__ A, const float* __restrict__ Bw,
                    const float* __restrict__ bias, float* __restrict__ C,
                    int M, int Nn, int K)
{
    __shared__ float As[GBK][GLDA];
    __shared__ float Bs[GBK][GLDA];

    const int tid = threadIdx.x;
    const int tx = tid & 15;
    const int ty = tid >> 4;
    const int mBase = blockIdx.y * GBM;
    const int nBase = blockIdx.x * GBN;

    unsigned long long acc[8][4];
#pragma unroll
    for (int i = 0; i < 8; ++i)
#pragma unroll
        for (int j = 0; j < 4; ++j) acc[i][j] = 0ULL;

    for (int k0 = 0; k0 < K; k0 += GBK) {
#pragma unroll
        for (int f = 0; f < 2; ++f) {
            int lin = tid + f * 256;
            int r  = lin >> 2;
            int kq = (lin & 3) << 2;
            float4 a = *(const float4*)&A[(size_t)(mBase + r) * K + k0 + kq];
            As[kq + 0][r] = a.x; As[kq + 1][r] = a.y;
            As[kq + 2][r] = a.z; As[kq + 3][r] = a.w;
            float4 b = *(const float4*)&Bw[(size_t)(nBase + r) * K + k0 + kq];
            Bs[kq + 0][r] = b.x; Bs[kq + 1][r] = b.y;
            Bs[kq + 2][r] = b.z; Bs[kq + 3][r] = b.w;
        }
        __syncthreads();

#pragma unroll
        for (int kk = 0; kk < GBK; ++kk) {
            float a[8];
            *(float4*)&a[0] = *(const float4*)&As[kk][ty * 8];
            *(float4*)&a[4] = *(const float4*)&As[kk][ty * 8 + 4];
            ulonglong2 blov = *(const ulonglong2*)&Bs[kk][tx * 8];
            ulonglong2 bhiv = *(const ulonglong2*)&Bs[kk][tx * 8 + 4];
            unsigned long long b2[4] = {blov.x, blov.y, bhiv.x, bhiv.y};
#pragma unroll
            for (int i = 0; i < 8; ++i) {
                unsigned long long a2 = pk2(a[i]);
#pragma unroll
                for (int j = 0; j < 4; ++j) fma2(acc[i][j], a2, b2[j]);
            }
        }
        __syncthreads();
    }

#pragma unroll
    for (int i = 0; i < 8; ++i) {
        int m = mBase + ty * 8 + i;
        float* crow = &C[(size_t)m * Nn + nBase + tx * 8];
#pragma unroll
        for (int jj = 0; jj < 2; ++jj) {
            float4 o;
            o.x = lo32(acc[i][jj * 2 + 0]);
            o.y = hi32(acc[i][jj * 2 + 0]);
            o.z = lo32(acc[i][jj * 2 + 1]);
            o.w = hi32(acc[i][jj * 2 + 1]);
            if (bias) {
                const float* bb = &bias[nBase + tx * 8 + jj * 4];
                o.x += bb[0]; o.y += bb[1]; o.z += bb[2]; o.w += bb[3];
            }
            *(float4*)&crow[jj * 4] = o;
        }
    }
}

// =====================================================================
// NAIVE rmsnorm + rope + split (UNCHANGED from R4 — proven correct).
// =====================================================================
__global__ void naive_norm_rope(const float* __restrict__ pos,
                                const float* __restrict__ qn_w,
                                const float* __restrict__ kn_w)
{
    int idx = blockIdx.x * blockDim.x + threadIdx.x;
    if (idx >= BATCH * SEQ * NH) return;
    int h   = idx % NH;
    int tok = idx / NH;
    int b = tok / SEQ, n = tok % SEQ;

    const float* row = g_qkv + (size_t)tok * (3 * DIM) + h * DH;
    float q[DH], k[DH], v[DH];
    float sq = 0.f, sk = 0.f;
    for (int d = 0; d < DH; ++d) {
        q[d] = row[d];
        k[d] = row[DIM + d];
        v[d] = row[2 * DIM + d];
        sq += q[d] * q[d];
        sk += k[d] * k[d];
    }
    float rq = rsqrtf(sq / DH + 1e-6f);
    float rk = rsqrtf(sk / DH + 1e-6f);
    for (int d = 0; d < DH; ++d) {
        q[d] *= rq * qn_w[d];
        k[d] *= rk * kn_w[d];
    }

    for (int p = 0; p < ROPE_DIM / 2; ++p) {
        int axis = p / HALF;
        int j = p - axis * HALF;
        float freq = powf(10000.0f, -(float)j / (float)HALF);
        float ang = pos[(size_t)tok * 3 + axis] * freq;
        float c = cosf(ang), s = sinf(ang);
        float qe = q[2*p] * c - q[2*p+1] * s;
        float qo = q[2*p] * s + q[2*p+1] * c;
        q[2*p] = qe; q[2*p+1] = qo;
        float ke = k[2*p] * c - k[2*p+1] * s;
        float ko = k[2*p] * s + k[2*p+1] * c;
        k[2*p] = ke; k[2*p+1] = ko;
    }

    size_t ob = ((size_t)(b * NH + h) * SEQ + n) * DH;
    for (int d = 0; d < DH; ++d) {
        g_q[ob + d] = q[d];
        g_k[ob + d] = k[d];
        g_v[ob + d] = v[d];
    }
}

// =====================================================================
// Tiled flash attention v2 (NEW LOGIC vs the buggy R2/R3 kernel):
//  - softmax row reductions via smem scratch (no shuffle-replicated state)
//  - P kept in natural [q][k] smem layout (no transpose round-trip)
// Block: 256 threads, one (bh, 64-query tile). Key tiles of 64.
// Thread (ty,tx): S rows q0=4ty x cols 4tx; O rows q0 x dims d0=4tx.
// =====================================================================
#define SP 68            // padded row stride (floats)
#define RSP 17           // reduction scratch stride

__global__ __launch_bounds__(256)
void attn2_kernel()
{
    extern __shared__ float sm[];
    float* Qt   = sm;               // [d][q]  Qt[d*SP+q] = Q[q][d]
    float* Kt   = Qt + 64 * SP;     // [d][k]  Kt[d*SP+k] = K[k][d]
    float* Vs   = Kt + 64 * SP;     // [k][d]  natural
    float* Ss   = Vs + 64 * SP;     // [q][k]  P matrix, natural
    float* redA = Ss + 64 * SP;     // [64][RSP] row-max partials
    float* redB = redA + 64 * RSP;  // [64][RSP] row-sum partials

    const int tid = threadIdx.x;
    const int tx = tid & 15, ty = tid >> 4;
    const int q0 = ty * 4, d0 = tx * 4;
    const int bh = blockIdx.y;           // b*NH + h
    const int b  = bh / NH, h = bh % NH;
    const int n0 = blockIdx.x * 64;

    // ---- load Q tile into d-major smem (row-fast => conflict-free STS,
    //      L1 absorbs the strided gmem pattern) ----
    const float* Qg = g_q + ((size_t)bh * SEQ + n0) * DH;
    for (int idx = tid; idx < 64 * 64; idx += 256) {
        int r = idx & 63, d = idx >> 6;
        Qt[d * SP + r] = Qg[r * DH + d];
    }

    float m[4], l[4];
    unsigned long long o2[4][2];
#pragma unroll
    for (int i = 0; i < 4; ++i) {
        m[i] = -INFINITY; l[i] = 0.f;
        o2[i][0] = 0ULL; o2[i][1] = 0ULL;
    }

    for (int kt = 0; kt < SEQ / 64; ++kt) {
        const float* Kg = g_k + ((size_t)bh * SEQ + kt * 64) * DH;
        const float* Vg = g_v + ((size_t)bh * SEQ + kt * 64) * DH;
        for (int idx = tid; idx < 64 * 64; idx += 256) {
            int r = idx & 63, d = idx >> 6;
            Kt[d * SP + r] = Kg[r * DH + d];     // d-major
            Vs[(idx >> 6) * SP + (idx & 63)] = Vg[idx];  // natural [k][d]
        }
        __syncthreads();   // (1) tiles + (first iter) Qt visible

        // ---- S = Q K^T * scale ----
        unsigned long long s2[4][2];
#pragma unroll
        for (int i = 0; i < 4; ++i) { s2[i][0] = 0ULL; s2[i][1] = 0ULL; }
#pragma unroll 8
        for (int d = 0; d < 64; ++d) {
            float4 av = *(const float4*)&Qt[d * SP + q0];
            ulonglong2 bv = *(const ulonglong2*)&Kt[d * SP + tx * 4];
            float aa[4] = {av.x, av.y, av.z, av.w};
#pragma unroll
            for (int i = 0; i < 4; ++i) {
                unsigned long long a2 = pk2(aa[i]);
                fma2(s2[i][0], a2, bv.x);
                fma2(s2[i][1], a2, bv.y);
            }
        }
        float S[4][4];
#pragma unroll
        for (int i = 0; i < 4; ++i) {
            S[i][0] = lo32(s2[i][0]) * 0.125f;
            S[i][1] = hi32(s2[i][0]) * 0.125f;
            S[i][2] = lo32(s2[i][1]) * 0.125f;
            S[i][3] = hi32(s2[i][1]) * 0.125f;
        }

        // ---- row max via smem scratch ----
#pragma unroll
        for (int i = 0; i < 4; ++i)
            redA[(q0 + i) * RSP + tx] =
                fmaxf(fmaxf(S[i][0], S[i][1]), fmaxf(S[i][2], S[i][3]));
        __syncthreads();   // (2)

        float mn[4], alpha[4];
#pragma unroll
        for (int i = 0; i < 4; ++i) {
            const float* rr = &redA[(q0 + i) * RSP];
            float mx = rr[0];
#pragma unroll
            for (int t = 1; t < 16; ++t) mx = fmaxf(mx, rr[t]);
            mn[i] = fmaxf(m[i], mx);
            alpha[i] = __expf(m[i] - mn[i]);
            m[i] = mn[i];
        }

        // ---- P = exp(S - mn); write P to Ss (natural layout) + partial sums
#pragma unroll
        for (int i = 0; i < 4; ++i) {
            float4 p;
            p.x = __expf(S[i][0] - mn[i]);
            p.y = __expf(S[i][1] - mn[i]);
            p.z = __expf(S[i][2] - mn[i]);
            p.w = __expf(S[i][3] - mn[i]);
            *(float4*)&Ss[(q0 + i) * SP + tx * 4] = p;
            redB[(q0 + i) * RSP + tx] = p.x + p.y + p.z + p.w;
        }
        __syncthreads();   // (3)

#pragma unroll
        for (int i = 0; i < 4; ++i) {
            const float* rr = &redB[(q0 + i) * RSP];
            float sum = rr[0];
#pragma unroll
            for (int t = 1; t < 16; ++t) sum += rr[t];
            l[i] = l[i] * alpha[i] + sum;
            unsigned long long a2 = pk2(alpha[i]);
            mul2(o2[i][0], a2);
            mul2(o2[i][1], a2);
        }

        // ---- O += P V ----
#pragma unroll 4
        for (int kk4 = 0; kk4 < 16; ++kk4) {
            float p[4][4];
#pragma unroll
            for (int i = 0; i < 4; ++i)
                *(float4*)&p[i][0] = *(const float4*)&Ss[(q0 + i) * SP + kk4 * 4];
#pragma unroll
            for (int j = 0; j < 4; ++j) {
                ulonglong2 vv = *(const ulonglong2*)&Vs[(kk4 * 4 + j) * SP + d0];
#pragma unroll
                for (int i = 0; i < 4; ++i) {
                    unsigned long long p2 = pk2(p[i][j]);
                    fma2(o2[i][0], p2, vv.x);
                    fma2(o2[i][1], p2, vv.y);
                }
            }
        }
        __syncthreads();   // (4) protect Vs/Kt/Ss before next tile
    }

    // ---- epilogue: O / l, write [b][n][h][d] ----
#pragma unroll
    for (int i = 0; i < 4; ++i) {
        unsigned long long inv2 = pk2(1.0f / l[i]);
        mul2(o2[i][0], inv2);
        mul2(o2[i][1], inv2);
        float4 o;
        o.x = lo32(o2[i][0]); o.y = hi32(o2[i][0]);
        o.z = lo32(o2[i][1]); o.w = hi32(o2[i][1]);
        size_t off = ((size_t)(b * SEQ + n0 + q0 + i) * NH + h) * DH + d0;
        *(float4*)&g_att[off] = o;
    }
}

// =====================================================================
// host launcher
// =====================================================================
extern "C" void kernel_launch(void* const* d_in, const int* in_sizes, int n_in,
                              void* d_out, int out_size)
{
    const float *x = 0, *pos = 0, *qkv_w = 0, *proj_w = 0, *proj_b = 0;
    const float *qn_w = 0, *kn_w = 0;
    for (int i = 0; i < n_in; ++i) {
        int s = in_sizes[i];
        const float* p = (const float*)d_in[i];
        if      (s == BATCH * SEQ * DIM)  x = p;
        else if (s == BATCH * SEQ * 3)    pos = p;
        else if (s == 3 * DIM * DIM)      qkv_w = p;
        else if (s == DIM * DIM)          proj_w = p;
        else if (s == DIM)                proj_b = p;
        else if (s == DH) { if (!qn_w) qn_w = p; else kn_w = p; }
    }
    float* out = (float*)d_out;

    float *qkv, *att;
    cudaGetSymbolAddress((void**)&qkv, g_qkv);
    cudaGetSymbolAddress((void**)&att, g_att);

    const int smem_attn = (4 * 64 * SP + 2 * 64 * RSP) * (int)sizeof(float); // 78336
    cudaFuncSetAttribute(attn2_kernel, cudaFuncAttributeMaxDynamicSharedMemorySize,
                         smem_attn);

    // 1) qkv = x @ qkv_w^T
    gemm_nt_kernel<<<dim3(3 * DIM / GBN, BATCH * SEQ / GBM), 256>>>(
        x, qkv_w, nullptr, qkv, BATCH * SEQ, 3 * DIM, DIM);

    // 2) rmsnorm + rope + split (proven naive version)
    {
        int total = BATCH * SEQ * NH;
        naive_norm_rope<<<(total + 127) / 128, 128>>>(pos, qn_w, kn_w);
    }

    // 3) tiled flash attention
    attn2_kernel<<<dim3(SEQ / 64, BATCH * NH), 256, smem_attn>>>();

    // 4) out = att @ proj_w^T + proj_b
    gemm_nt_kernel<<<dim3(DIM / GBN, BATCH * SEQ / GBM), 256>>>(
        att, proj_w, proj_b, out, BATCH * SEQ, DIM, DIM);
}

// round 8
// speedup vs baseline: 2.2872x; 1.0880x over previous
#include <cuda_runtime.h>
#include <cuda_bf16.h>
#include <math.h>

// Problem constants
#define BATCH 2
#define SEQ   2048
#define DIM   768
#define NH    12
#define DH    64
#define ROPE_DIM 60
#define HALF  10
#define NT    (SEQ / 64)   // 32 key tiles

// ---------------- scratch (static device arrays; no allocation) -------------
__device__ float g_qkv[BATCH * SEQ * 3 * DIM];
__device__ float g_q[BATCH * NH * SEQ * DH];
__device__ float g_k[BATCH * NH * SEQ * DH];
__device__ float g_v[BATCH * NH * SEQ * DH];
__device__ float g_att[BATCH * SEQ * DIM];

// ---------------- f32x2 packed helpers --------------------------------------
__device__ __forceinline__ unsigned long long pk2(float x) {
    unsigned long long r;
    asm("mov.b64 %0, {%1, %1};" : "=l"(r) : "r"(__float_as_uint(x)));
    return r;
}
__device__ __forceinline__ void fma2(unsigned long long &d,
                                     unsigned long long a, unsigned long long b) {
    asm("fma.rn.f32x2 %0, %1, %2, %3;" : "=l"(d) : "l"(a), "l"(b), "l"(d));
}
__device__ __forceinline__ void mul2(unsigned long long &d, unsigned long long a) {
    asm("mul.rn.f32x2 %0, %1, %2;" : "=l"(d) : "l"(d), "l"(a));
}
__device__ __forceinline__ float lo32(unsigned long long v) {
    return __uint_as_float((unsigned)(v & 0xffffffffULL));
}
__device__ __forceinline__ float hi32(unsigned long long v) {
    return __uint_as_float((unsigned)(v >> 32));
}

// ---------------- cp.async helpers ------------------------------------------
__device__ __forceinline__ void cp_async16(void* smem_dst, const void* gmem_src) {
    unsigned s = (unsigned)__cvta_generic_to_shared(smem_dst);
    asm volatile("cp.async.cg.shared.global [%0], [%1], 16;" :: "r"(s), "l"(gmem_src));
}
__device__ __forceinline__ void cp_commit() {
    asm volatile("cp.async.commit_group;");
}
template<int N>
__device__ __forceinline__ void cp_wait() {
    asm volatile("cp.async.wait_group %0;" :: "n"(N));
}

// =====================================================================
// GEMM: C = A * B^T (+bias). 128x128x16, 256 thr, 8x8/thread, f32x2.
// (unchanged — certified R4/R5)
// =====================================================================
#define GBM 128
#define GBN 128
#define GBK 16
#define GLDA (GBM + 4)

__global__ __launch_bounds__(256, 2)
void gemm_nt_kernel(const float* __restrict__ A, const float* __restrict__ Bw,
                    const float* __restrict__ bias, float* __restrict__ C,
                    int M, int Nn, int K)
{
    __shared__ float As[GBK][GLDA];
    __shared__ float Bs[GBK][GLDA];

    const int tid = threadIdx.x;
    const int tx = tid & 15;
    const int ty = tid >> 4;
    const int mBase = blockIdx.y * GBM;
    const int nBase = blockIdx.x * GBN;

    unsigned long long acc[8][4];
#pragma unroll
    for (int i = 0; i < 8; ++i)
#pragma unroll
        for (int j = 0; j < 4; ++j) acc[i][j] = 0ULL;

    for (int k0 = 0; k0 < K; k0 += GBK) {
#pragma unroll
        for (int f = 0; f < 2; ++f) {
            int lin = tid + f * 256;
            int r  = lin >> 2;
            int kq = (lin & 3) << 2;
            float4 a = *(const float4*)&A[(size_t)(mBase + r) * K + k0 + kq];
            As[kq + 0][r] = a.x; As[kq + 1][r] = a.y;
            As[kq + 2][r] = a.z; As[kq + 3][r] = a.w;
            float4 b = *(const float4*)&Bw[(size_t)(nBase + r) * K + k0 + kq];
            Bs[kq + 0][r] = b.x; Bs[kq + 1][r] = b.y;
            Bs[kq + 2][r] = b.z; Bs[kq + 3][r] = b.w;
        }
        __syncthreads();

#pragma unroll
        for (int kk = 0; kk < GBK; ++kk) {
            float a[8];
            *(float4*)&a[0] = *(const float4*)&As[kk][ty * 8];
            *(float4*)&a[4] = *(const float4*)&As[kk][ty * 8 + 4];
            ulonglong2 blov = *(const ulonglong2*)&Bs[kk][tx * 8];
            ulonglong2 bhiv = *(const ulonglong2*)&Bs[kk][tx * 8 + 4];
            unsigned long long b2[4] = {blov.x, blov.y, bhiv.x, bhiv.y};
#pragma unroll
            for (int i = 0; i < 8; ++i) {
                unsigned long long a2 = pk2(a[i]);
#pragma unroll
                for (int j = 0; j < 4; ++j) fma2(acc[i][j], a2, b2[j]);
            }
        }
        __syncthreads();
    }

#pragma unroll
    for (int i = 0; i < 8; ++i) {
        int m = mBase + ty * 8 + i;
        float* crow = &C[(size_t)m * Nn + nBase + tx * 8];
#pragma unroll
        for (int jj = 0; jj < 2; ++jj) {
            float4 o;
            o.x = lo32(acc[i][jj * 2 + 0]);
            o.y = hi32(acc[i][jj * 2 + 0]);
            o.z = lo32(acc[i][jj * 2 + 1]);
            o.w = hi32(acc[i][jj * 2 + 1]);
            if (bias) {
                const float* bb = &bias[nBase + tx * 8 + jj * 4];
                o.x += bb[0]; o.y += bb[1]; o.z += bb[2]; o.w += bb[3];
            }
            *(float4*)&crow[jj * 4] = o;
        }
    }
}

// =====================================================================
// Warp-parallel rmsnorm + rope + split. One warp per (b,n,h).
// =====================================================================
__global__ void norm_rope_warp(const float* __restrict__ pos,
                               const float* __restrict__ qn_w,
                               const float* __restrict__ kn_w)
{
    int gw = (blockIdx.x * blockDim.x + threadIdx.x) >> 5;
    int t  = threadIdx.x & 31;
    if (gw >= BATCH * SEQ * NH) return;
    int h   = gw % NH;
    int tok = gw / NH;
    int b = tok / SEQ, n = tok % SEQ;

    const size_t base = (size_t)tok * (3 * DIM) + h * DH + 2 * t;
    float2 qv = *(const float2*)&g_qkv[base];
    float2 kv = *(const float2*)&g_qkv[base + DIM];
    float2 vv = *(const float2*)&g_qkv[base + 2 * DIM];

    float sq = qv.x * qv.x + qv.y * qv.y;
    float sk = kv.x * kv.x + kv.y * kv.y;
#pragma unroll
    for (int o = 16; o; o >>= 1) {
        sq += __shfl_xor_sync(0xffffffffu, sq, o);
        sk += __shfl_xor_sync(0xffffffffu, sk, o);
    }
    float rq = rsqrtf(sq * (1.0f / DH) + 1e-6f);
    float rk = rsqrtf(sk * (1.0f / DH) + 1e-6f);
    qv.x *= rq * qn_w[2 * t]; qv.y *= rq * qn_w[2 * t + 1];
    kv.x *= rk * kn_w[2 * t]; kv.y *= rk * kn_w[2 * t + 1];

    if (t < ROPE_DIM / 2) {
        int axis = t / HALF;
        int j = t - axis * HALF;
        float freq = powf(10000.0f, -(float)j / (float)HALF);
        float ang = pos[(size_t)tok * 3 + axis] * freq;
        float c = cosf(ang), s = sinf(ang);
        float qe = qv.x * c - qv.y * s, qo = qv.x * s + qv.y * c;
        qv.x = qe; qv.y = qo;
        float ke = kv.x * c - kv.y * s, ko = kv.x * s + kv.y * c;
        kv.x = ke; kv.y = ko;
    }

    const size_t ob = ((size_t)(b * NH + h) * SEQ + n) * DH + 2 * t;
    *(float2*)&g_q[ob] = qv;
    *(float2*)&g_k[ob] = kv;
    *(float2*)&g_v[ob] = vv;
}

// =====================================================================
// Flash attention v3.1: no-max softmax, double-buffered K (reg prefetch)
// + V (cp.async). RACE FIX vs R7: next-V cp.async is issued AFTER the
// top-of-iteration barrier, so the target buffer's prior readers are
// provably done. 2 syncthreads per key tile.
// =====================================================================
#define SP 68

__global__ __launch_bounds__(256)
void attn3_kernel()
{
    extern __shared__ float sm[];
    float* Qt = sm;                       // [d][q]
    float* Kt0 = Qt + 64 * SP;            // [d][k] buffer 0
    float* Kt1 = Kt0 + 64 * SP;           // buffer 1
    float* Vs0 = Kt1 + 64 * SP;           // [k][d] buffer 0
    float* Vs1 = Vs0 + 64 * SP;           // buffer 1
    float* Ss  = Vs1 + 64 * SP;           // [q][k] P tile (+reduction scratch)

    const int tid = threadIdx.x;
    const int tx = tid & 15, ty = tid >> 4;
    const int q0 = ty * 4, c0 = tx * 4;
    const int bh = blockIdx.y;
    const int b  = bh / NH, h = bh % NH;
    const int n0 = blockIdx.x * 64;

    const float* Qg = g_q + ((size_t)bh * SEQ + n0) * DH;
    const float* Kg = g_k + (size_t)bh * SEQ * DH;
    const float* Vg = g_v + (size_t)bh * SEQ * DH;

    const int lr = tid & 63;              // gmem row within tile
    const int ld = tid >> 6;              // base dim (0..3), step 4 per e

    // ---- Q tile (transpose into d-major) ----
#pragma unroll
    for (int e = 0; e < 16; ++e) {
        int d = ld + e * 4;
        Qt[d * SP + lr] = Qg[lr * DH + d];
    }

    // ---- preload tile 0 ----
#pragma unroll
    for (int e = 0; e < 16; ++e) {
        int d = ld + e * 4;
        Kt0[d * SP + lr] = Kg[lr * DH + d];
    }
#pragma unroll
    for (int e = 0; e < 4; ++e) {
        int fidx = tid + e * 256;
        int r = fidx >> 4, dq = (fidx & 15) * 4;
        cp_async16(&Vs0[r * SP + dq], &Vg[r * DH + dq]);
    }
    cp_commit();
    cp_wait<0>();
    __syncthreads();   // == sync (A) for kt=0: tile-0 buffers ready

    unsigned long long o2[4][2];
    float lsum[4];
#pragma unroll
    for (int i = 0; i < 4; ++i) {
        o2[i][0] = 0ULL; o2[i][1] = 0ULL; lsum[i] = 0.f;
    }

    for (int kt = 0; kt < NT; ++kt) {
        float* Ktc = (kt & 1) ? Kt1 : Kt0;
        float* Vsc = (kt & 1) ? Vs1 : Vs0;
        float* Ktn = (kt & 1) ? Kt0 : Kt1;
        float* Vsn = (kt & 1) ? Vs0 : Vs1;

        // ---- prefetch next tile. SAFE: we are past sync (A), so every
        // thread finished iteration kt-1 → no one still reads Vsn/Ktn. ----
        float kreg[16];
        if (kt + 1 < NT) {
            const float* Kgn = Kg + (size_t)(kt + 1) * 64 * DH;
            const float* Vgn = Vg + (size_t)(kt + 1) * 64 * DH;
#pragma unroll
            for (int e = 0; e < 4; ++e) {
                int fidx = tid + e * 256;
                int r = fidx >> 4, dq = (fidx & 15) * 4;
                cp_async16(&Vsn[r * SP + dq], &Vgn[r * DH + dq]);
            }
            cp_commit();
#pragma unroll
            for (int e = 0; e < 16; ++e)
                kreg[e] = Kgn[lr * DH + ld + e * 4];
        }

        // ---- S = Q K^T ----
        unsigned long long s2[4][2];
#pragma unroll
        for (int i = 0; i < 4; ++i) { s2[i][0] = 0ULL; s2[i][1] = 0ULL; }
#pragma unroll 8
        for (int d = 0; d < 64; ++d) {
            float4 av = *(const float4*)&Qt[d * SP + q0];
            ulonglong2 bv = *(const ulonglong2*)&Ktc[d * SP + c0];
            float aa[4] = {av.x, av.y, av.z, av.w};
#pragma unroll
            for (int i = 0; i < 4; ++i) {
                unsigned long long a2 = pk2(aa[i]);
                fma2(s2[i][0], a2, bv.x);
                fma2(s2[i][1], a2, bv.y);
            }
        }

        // ---- P = exp(S*scale); partial row sums; stage to smem ----
#pragma unroll
        for (int i = 0; i < 4; ++i) {
            float4 p;
            p.x = __expf(lo32(s2[i][0]) * 0.125f);
            p.y = __expf(hi32(s2[i][0]) * 0.125f);
            p.z = __expf(lo32(s2[i][1]) * 0.125f);
            p.w = __expf(hi32(s2[i][1]) * 0.125f);
            *(float4*)&Ss[(q0 + i) * SP + c0] = p;
            lsum[i] += p.x + p.y + p.z + p.w;
        }
        __syncthreads();      // (B) P visible

        // ---- O += P V ----
#pragma unroll 4
        for (int kk4 = 0; kk4 < 16; ++kk4) {
            float p[4][4];
#pragma unroll
            for (int i = 0; i < 4; ++i)
                *(float4*)&p[i][0] = *(const float4*)&Ss[(q0 + i) * SP + kk4 * 4];
#pragma unroll
            for (int j = 0; j < 4; ++j) {
                ulonglong2 vv = *(const ulonglong2*)&Vsc[(kk4 * 4 + j) * SP + c0];
#pragma unroll
                for (int i = 0; i < 4; ++i) {
                    unsigned long long p2 = pk2(p[i][j]);
                    fma2(o2[i][0], p2, vv.x);
                    fma2(o2[i][1], p2, vv.y);
                }
            }
        }

        // ---- stage next K tile regs -> smem (Ktn readers done pre-sync A)
        if (kt + 1 < NT) {
#pragma unroll
            for (int e = 0; e < 16; ++e)
                Ktn[(ld + e * 4) * SP + lr] = kreg[e];
        }

        cp_wait<0>();         // next-V landed (issued this iteration)
        __syncthreads();      // (A) next buffers ready+visible; Ss free
    }

    // ---- final row-sum reduction, scale, write ----
#pragma unroll
    for (int i = 0; i < 4; ++i)
        Ss[(q0 + i) * SP + tx] = lsum[i];
    __syncthreads();

#pragma unroll
    for (int i = 0; i < 4; ++i) {
        const float* rr = &Ss[(q0 + i) * SP];
        float l = rr[0];
#pragma unroll
        for (int t = 1; t < 16; ++t) l += rr[t];
        unsigned long long inv2 = pk2(1.0f / l);
        mul2(o2[i][0], inv2);
        mul2(o2[i][1], inv2);
        float4 o;
        o.x = lo32(o2[i][0]); o.y = hi32(o2[i][0]);
        o.z = lo32(o2[i][1]); o.w = hi32(o2[i][1]);
        size_t off = ((size_t)(b * SEQ + n0 + q0 + i) * NH + h) * DH + c0;
        *(float4*)&g_att[off] = o;
    }
}

// =====================================================================
// host launcher
// =====================================================================
extern "C" void kernel_launch(void* const* d_in, const int* in_sizes, int n_in,
                              void* d_out, int out_size)
{
    const float *x = 0, *pos = 0, *qkv_w = 0, *proj_w = 0, *proj_b = 0;
    const float *qn_w = 0, *kn_w = 0;
    for (int i = 0; i < n_in; ++i) {
        int s = in_sizes[i];
        const float* p = (const float*)d_in[i];
        if      (s == BATCH * SEQ * DIM)  x = p;
        else if (s == BATCH * SEQ * 3)    pos = p;
        else if (s == 3 * DIM * DIM)      qkv_w = p;
        else if (s == DIM * DIM)          proj_w = p;
        else if (s == DIM)                proj_b = p;
        else if (s == DH) { if (!qn_w) qn_w = p; else kn_w = p; }
    }
    float* out = (float*)d_out;

    float *qkv, *att;
    cudaGetSymbolAddress((void**)&qkv, g_qkv);
    cudaGetSymbolAddress((void**)&att, g_att);

    const int smem_attn = 6 * 64 * SP * (int)sizeof(float);   // 104448 B
    cudaFuncSetAttribute(attn3_kernel, cudaFuncAttributeMaxDynamicSharedMemorySize,
                         smem_attn);

    // 1) qkv = x @ qkv_w^T
    gemm_nt_kernel<<<dim3(3 * DIM / GBN, BATCH * SEQ / GBM), 256>>>(
        x, qkv_w, nullptr, qkv, BATCH * SEQ, 3 * DIM, DIM);

    // 2) rmsnorm + rope + split (warp-parallel)
    {
        int totalWarps = BATCH * SEQ * NH;
        int threads = 256;
        int blocks = (totalWarps * 32 + threads - 1) / threads;
        norm_rope_warp<<<blocks, threads>>>(pos, qn_w, kn_w);
    }

    // 3) flash attention v3.1
    attn3_kernel<<<dim3(SEQ / 64, BATCH * NH), 256, smem_attn>>>();

    // 4) out = att @ proj_w^T + proj_b
    gemm_nt_kernel<<<dim3(DIM / GBN, BATCH * SEQ / GBM), 256>>>(
        att, proj_w, proj_b, out, BATCH * SEQ, DIM, DIM);
}

// round 9
// speedup vs baseline: 2.7001x; 1.1805x over previous
#include <cuda_runtime.h>
#include <cuda_bf16.h>
#include <math.h>

// Problem constants
#define BATCH 2
#define SEQ   2048
#define DIM   768
#define NH    12
#define DH    64
#define ROPE_DIM 60
#define HALF  10
#define NT    (SEQ / 64)   // 32 key tiles of 64

// ---------------- scratch (static device arrays; no allocation) -------------
__device__ float g_qkv[BATCH * SEQ * 3 * DIM];
__device__ float g_q[BATCH * NH * SEQ * DH];
__device__ float g_k[BATCH * NH * SEQ * DH];
__device__ float g_v[BATCH * NH * SEQ * DH];
__device__ float g_att[BATCH * SEQ * DIM];

// ---------------- f32x2 packed helpers --------------------------------------
__device__ __forceinline__ unsigned long long pk2(float x) {
    unsigned long long r;
    asm("mov.b64 %0, {%1, %1};" : "=l"(r) : "r"(__float_as_uint(x)));
    return r;
}
__device__ __forceinline__ unsigned long long pack2(float lo, float hi) {
    unsigned long long r;
    asm("mov.b64 %0, {%1, %2};" : "=l"(r) : "r"(__float_as_uint(lo)), "r"(__float_as_uint(hi)));
    return r;
}
__device__ __forceinline__ void fma2(unsigned long long &d,
                                     unsigned long long a, unsigned long long b) {
    asm("fma.rn.f32x2 %0, %1, %2, %3;" : "=l"(d) : "l"(a), "l"(b), "l"(d));
}
__device__ __forceinline__ void mul2(unsigned long long &d, unsigned long long a) {
    asm("mul.rn.f32x2 %0, %1, %2;" : "=l"(d) : "l"(d), "l"(a));
}
__device__ __forceinline__ void add2(unsigned long long &d, unsigned long long a) {
    asm("add.rn.f32x2 %0, %1, %2;" : "=l"(d) : "l"(d), "l"(a));
}
__device__ __forceinline__ float lo32(unsigned long long v) {
    return __uint_as_float((unsigned)(v & 0xffffffffULL));
}
__device__ __forceinline__ float hi32(unsigned long long v) {
    return __uint_as_float((unsigned)(v >> 32));
}

// ---------------- cp.async helpers ------------------------------------------
__device__ __forceinline__ void cp_async16(void* smem_dst, const void* gmem_src) {
    unsigned s = (unsigned)__cvta_generic_to_shared(smem_dst);
    asm volatile("cp.async.cg.shared.global [%0], [%1], 16;" :: "r"(s), "l"(gmem_src));
}
__device__ __forceinline__ void cp_commit() {
    asm volatile("cp.async.commit_group;");
}
template<int N>
__device__ __forceinline__ void cp_wait() {
    asm volatile("cp.async.wait_group %0;" :: "n"(N));
}

// =====================================================================
// GEMM v2: C = A*B^T (+bias). 128x128x16, 256 thr, 8x8/thread, f32x2,
// register-prefetch double-buffered smem, 1 sync per k-step.
// Inner-loop math identical to certified R4/R5 kernel.
// =====================================================================
#define GBM 128
#define GBN 128
#define GBK 16
#define GLDA (GBM + 4)

__global__ __launch_bounds__(256)
void gemm_nt_kernel(const float* __restrict__ A, const float* __restrict__ Bw,
                    const float* __restrict__ bias, float* __restrict__ C,
                    int M, int Nn, int K)
{
    __shared__ float As[2][GBK][GLDA];
    __shared__ float Bs[2][GBK][GLDA];

    const int tid = threadIdx.x;
    const int tx = tid & 15;
    const int ty = tid >> 4;
    const int mBase = blockIdx.y * GBM;
    const int nBase = blockIdx.x * GBN;

    // each thread fetches 2 float4 of A and 2 of B per tile
    const int r0  = tid >> 1;                 // rows for f=0 .. f=1: r0, r0+128? no:
    // lin = tid + 256f -> r = lin>>2, kq = (lin&3)<<2
    unsigned long long acc[8][4];
#pragma unroll
    for (int i = 0; i < 8; ++i)
#pragma unroll
        for (int j = 0; j < 4; ++j) acc[i][j] = 0ULL;

    float4 pa[2], pb[2];
    // prologue: fetch tile 0
#pragma unroll
    for (int f = 0; f < 2; ++f) {
        int lin = tid + f * 256;
        int r  = lin >> 2;
        int kq = (lin & 3) << 2;
        pa[f] = *(const float4*)&A[(size_t)(mBase + r) * K + kq];
        pb[f] = *(const float4*)&Bw[(size_t)(nBase + r) * K + kq];
    }
#pragma unroll
    for (int f = 0; f < 2; ++f) {
        int lin = tid + f * 256;
        int r  = lin >> 2;
        int kq = (lin & 3) << 2;
        As[0][kq + 0][r] = pa[f].x; As[0][kq + 1][r] = pa[f].y;
        As[0][kq + 2][r] = pa[f].z; As[0][kq + 3][r] = pa[f].w;
        Bs[0][kq + 0][r] = pb[f].x; Bs[0][kq + 1][r] = pb[f].y;
        Bs[0][kq + 2][r] = pb[f].z; Bs[0][kq + 3][r] = pb[f].w;
    }
    __syncthreads();

    const int nIter = K / GBK;
    for (int it = 0; it < nIter; ++it) {
        int cur = it & 1, nxt = cur ^ 1;

        // prefetch next tile into regs (no wait)
        if (it + 1 < nIter) {
            int k0 = (it + 1) * GBK;
#pragma unroll
            for (int f = 0; f < 2; ++f) {
                int lin = tid + f * 256;
                int r  = lin >> 2;
                int kq = (lin & 3) << 2;
                pa[f] = *(const float4*)&A[(size_t)(mBase + r) * K + k0 + kq];
                pb[f] = *(const float4*)&Bw[(size_t)(nBase + r) * K + k0 + kq];
            }
        }

        // compute from cur
#pragma unroll
        for (int kk = 0; kk < GBK; ++kk) {
            float a[8];
            *(float4*)&a[0] = *(const float4*)&As[cur][kk][ty * 8];
            *(float4*)&a[4] = *(const float4*)&As[cur][kk][ty * 8 + 4];
            ulonglong2 blov = *(const ulonglong2*)&Bs[cur][kk][tx * 8];
            ulonglong2 bhiv = *(const ulonglong2*)&Bs[cur][kk][tx * 8 + 4];
            unsigned long long b2[4] = {blov.x, blov.y, bhiv.x, bhiv.y};
#pragma unroll
            for (int i = 0; i < 8; ++i) {
                unsigned long long a2 = pk2(a[i]);
#pragma unroll
                for (int j = 0; j < 4; ++j) fma2(acc[i][j], a2, b2[j]);
            }
        }

        // stage regs -> nxt buffer (readers of nxt finished before last sync)
        if (it + 1 < nIter) {
#pragma unroll
            for (int f = 0; f < 2; ++f) {
                int lin = tid + f * 256;
                int r  = lin >> 2;
                int kq = (lin & 3) << 2;
                As[nxt][kq + 0][r] = pa[f].x; As[nxt][kq + 1][r] = pa[f].y;
                As[nxt][kq + 2][r] = pa[f].z; As[nxt][kq + 3][r] = pa[f].w;
                Bs[nxt][kq + 0][r] = pb[f].x; Bs[nxt][kq + 1][r] = pb[f].y;
                Bs[nxt][kq + 2][r] = pb[f].z; Bs[nxt][kq + 3][r] = pb[f].w;
            }
        }
        __syncthreads();
    }

#pragma unroll
    for (int i = 0; i < 8; ++i) {
        int m = mBase + ty * 8 + i;
        float* crow = &C[(size_t)m * Nn + nBase + tx * 8];
#pragma unroll
        for (int jj = 0; jj < 2; ++jj) {
            float4 o;
            o.x = lo32(acc[i][jj * 2 + 0]);
            o.y = hi32(acc[i][jj * 2 + 0]);
            o.z = lo32(acc[i][jj * 2 + 1]);
            o.w = hi32(acc[i][jj * 2 + 1]);
            if (bias) {
                const float* bb = &bias[nBase + tx * 8 + jj * 4];
                o.x += bb[0]; o.y += bb[1]; o.z += bb[2]; o.w += bb[3];
            }
            *(float4*)&crow[jj * 4] = o;
        }
    }
}

// =====================================================================
// Warp-parallel rmsnorm + rope + split (unchanged, certified R8).
// =====================================================================
__global__ void norm_rope_warp(const float* __restrict__ pos,
                               const float* __restrict__ qn_w,
                               const float* __restrict__ kn_w)
{
    int gw = (blockIdx.x * blockDim.x + threadIdx.x) >> 5;
    int t  = threadIdx.x & 31;
    if (gw >= BATCH * SEQ * NH) return;
    int h   = gw % NH;
    int tok = gw / NH;
    int b = tok / SEQ, n = tok % SEQ;

    const size_t base = (size_t)tok * (3 * DIM) + h * DH + 2 * t;
    float2 qv = *(const float2*)&g_qkv[base];
    float2 kv = *(const float2*)&g_qkv[base + DIM];
    float2 vv = *(const float2*)&g_qkv[base + 2 * DIM];

    float sq = qv.x * qv.x + qv.y * qv.y;
    float sk = kv.x * kv.x + kv.y * kv.y;
#pragma unroll
    for (int o = 16; o; o >>= 1) {
        sq += __shfl_xor_sync(0xffffffffu, sq, o);
        sk += __shfl_xor_sync(0xffffffffu, sk, o);
    }
    float rq = rsqrtf(sq * (1.0f / DH) + 1e-6f);
    float rk = rsqrtf(sk * (1.0f / DH) + 1e-6f);
    qv.x *= rq * qn_w[2 * t]; qv.y *= rq * qn_w[2 * t + 1];
    kv.x *= rk * kn_w[2 * t]; kv.y *= rk * kn_w[2 * t + 1];

    if (t < ROPE_DIM / 2) {
        int axis = t / HALF;
        int j = t - axis * HALF;
        float freq = powf(10000.0f, -(float)j / (float)HALF);
        float ang = pos[(size_t)tok * 3 + axis] * freq;
        float c = cosf(ang), s = sinf(ang);
        float qe = qv.x * c - qv.y * s, qo = qv.x * s + qv.y * c;
        qv.x = qe; qv.y = qo;
        float ke = kv.x * c - kv.y * s, ko = kv.x * s + kv.y * c;
        kv.x = ke; kv.y = ko;
    }

    const size_t ob = ((size_t)(b * NH + h) * SEQ + n) * DH + 2 * t;
    *(float2*)&g_q[ob] = qv;
    *(float2*)&g_k[ob] = kv;
    *(float2*)&g_v[ob] = vv;
}

// =====================================================================
// Flash attention v4: q-tile 128, k-tile 64, per-thread 8q x 4k fragment
// with q-pair f32x2 packing (wide operand loaded directly as 64-bit).
// No-max softmax (|S|<=8). Pipeline = certified R8 scheme:
// post-sync-A V cp.async, K reg-prefetch, 2 syncs/tile.
// =====================================================================
#define QP  132   // Qt row stride ([d][q], q=128+4)
#define KP  68    // Kt/Vs row stride (64+4)
#define SSP 132   // Ss row stride ([k][q])
#define RP  17    // reduction scratch stride

__global__ __launch_bounds__(256)
void attn4_kernel()
{
    extern __shared__ float sm[];
    float* Qt  = sm;                  // [64 d][QP]   Qt[d][q]
    float* Kt0 = Qt  + 64 * QP;       // [64 d][KP]   Kt[d][k]
    float* Kt1 = Kt0 + 64 * KP;
    float* Vs0 = Kt1 + 64 * KP;       // [64 k][KP]   Vs[k][d]
    float* Vs1 = Vs0 + 64 * KP;
    float* Ss  = Vs1 + 64 * KP;       // [64 k][SSP]  P^T: Ss[k][q]

    const int tid = threadIdx.x;
    const int tx = tid & 15, ty = tid >> 4;
    const int q0 = ty * 8;            // 8 q-rows (4 pairs)
    const int c0 = tx * 4;            // 4 k-cols (S) / 4 d-cols (PV, out)
    const int bh = blockIdx.y;
    const int b  = bh / NH, h = bh % NH;
    const int n0 = blockIdx.x * 128;

    const float* Qg = g_q + ((size_t)bh * SEQ + n0) * DH;
    const float* Kg = g_k + (size_t)bh * SEQ * DH;
    const float* Vg = g_v + (size_t)bh * SEQ * DH;

    // ---- Q tile: 128 rows x 64 d, transpose to Qt[d][q] ----
    {
        const int lr = tid & 127;         // q row
        const int d0b = (tid >> 7) * 32;  // d base (0 or 32)
#pragma unroll
        for (int e = 0; e < 8; ++e) {
            float4 qv = *(const float4*)&Qg[(size_t)lr * DH + d0b + e * 4];
            Qt[(d0b + e * 4 + 0) * QP + lr] = qv.x;
            Qt[(d0b + e * 4 + 1) * QP + lr] = qv.y;
            Qt[(d0b + e * 4 + 2) * QP + lr] = qv.z;
            Qt[(d0b + e * 4 + 3) * QP + lr] = qv.w;
        }
    }

    // K-prefetch thread mapping (64-row tiles)
    const int lrk = tid & 63;
    const int ldk = tid >> 6;             // 0..3

    // ---- preload tile 0 ----
#pragma unroll
    for (int e = 0; e < 16; ++e)
        Kt0[(ldk + e * 4) * KP + lrk] = Kg[(size_t)lrk * DH + ldk + e * 4];
#pragma unroll
    for (int e = 0; e < 4; ++e) {
        int fidx = tid + e * 256;
        int r = fidx >> 4, dq = (fidx & 15) * 4;
        cp_async16(&Vs0[r * KP + dq], &Vg[(size_t)r * DH + dq]);
    }
    cp_commit();
    cp_wait<0>();
    __syncthreads();   // sync (A) for kt=0

    unsigned long long o2[4][4];      // [q-pair][d-col]
    unsigned long long lsum2[4];      // packed per-pair row sums
#pragma unroll
    for (int qp = 0; qp < 4; ++qp) {
        lsum2[qp] = 0ULL;
#pragma unroll
        for (int j = 0; j < 4; ++j) o2[qp][j] = 0ULL;
    }

    for (int kt = 0; kt < NT; ++kt) {
        float* Ktc = (kt & 1) ? Kt1 : Kt0;
        float* Vsc = (kt & 1) ? Vs1 : Vs0;
        float* Ktn = (kt & 1) ? Kt0 : Kt1;
        float* Vsn = (kt & 1) ? Vs0 : Vs1;

        // ---- prefetch next tile (safe: past sync A) ----
        float kreg[16];
        if (kt + 1 < NT) {
            const float* Kgn = Kg + (size_t)(kt + 1) * 64 * DH;
            const float* Vgn = Vg + (size_t)(kt + 1) * 64 * DH;
#pragma unroll
            for (int e = 0; e < 4; ++e) {
                int fidx = tid + e * 256;
                int r = fidx >> 4, dq = (fidx & 15) * 4;
                cp_async16(&Vsn[r * KP + dq], &Vgn[(size_t)r * DH + dq]);
            }
            cp_commit();
#pragma unroll
            for (int e = 0; e < 16; ++e)
                kreg[e] = Kgn[(size_t)lrk * DH + ldk + e * 4];
        }

        // ---- S = Q K^T : s2[qp][j], pair over q ----
        unsigned long long s2[4][4];
#pragma unroll
        for (int qp = 0; qp < 4; ++qp)
#pragma unroll
            for (int j = 0; j < 4; ++j) s2[qp][j] = 0ULL;

#pragma unroll 8
        for (int d = 0; d < 64; ++d) {
            ulonglong2 a01 = *(const ulonglong2*)&Qt[d * QP + q0];
            ulonglong2 a23 = *(const ulonglong2*)&Qt[d * QP + q0 + 4];
            float4 bv = *(const float4*)&Ktc[d * KP + c0];
            unsigned long long b2[4] = {pk2(bv.x), pk2(bv.y), pk2(bv.z), pk2(bv.w)};
            unsigned long long a2[4] = {a01.x, a01.y, a23.x, a23.y};
#pragma unroll
            for (int qp = 0; qp < 4; ++qp)
#pragma unroll
                for (int j = 0; j < 4; ++j) fma2(s2[qp][j], a2[qp], b2[j]);
        }

        // ---- P = exp(S/8): pack pairs, store P^T, accumulate row sums ----
#pragma unroll
        for (int qp = 0; qp < 4; ++qp)
#pragma unroll
            for (int j = 0; j < 4; ++j) {
                float plo = __expf(lo32(s2[qp][j]) * 0.125f);
                float phi = __expf(hi32(s2[qp][j]) * 0.125f);
                unsigned long long p2 = pack2(plo, phi);
                *(unsigned long long*)&Ss[(c0 + j) * SSP + q0 + 2 * qp] = p2;
                add2(lsum2[qp], p2);
            }
        __syncthreads();   // (B) P visible

        // ---- O += P V : wide operand = q-pairs straight from Ss ----
#pragma unroll 4
        for (int kk = 0; kk < 64; ++kk) {
            ulonglong2 pA = *(const ulonglong2*)&Ss[kk * SSP + q0];
            ulonglong2 pB = *(const ulonglong2*)&Ss[kk * SSP + q0 + 4];
            float4 vv = *(const float4*)&Vsc[kk * KP + c0];
            unsigned long long v2[4] = {pk2(vv.x), pk2(vv.y), pk2(vv.z), pk2(vv.w)};
            unsigned long long p2v[4] = {pA.x, pA.y, pB.x, pB.y};
#pragma unroll
            for (int qp = 0; qp < 4; ++qp)
#pragma unroll
                for (int j = 0; j < 4; ++j) fma2(o2[qp][j], p2v[qp], v2[j]);
        }

        // ---- stage next K regs -> other buffer ----
        if (kt + 1 < NT) {
#pragma unroll
            for (int e = 0; e < 16; ++e)
                Ktn[(ldk + e * 4) * KP + lrk] = kreg[e];
        }

        cp_wait<0>();
        __syncthreads();   // (A) next buffers ready; Ss free
    }

    // ---- final row-sum reduction (reuse Kt0 as scratch [128][RP]) ----
    float* red = Kt0;
#pragma unroll
    for (int qp = 0; qp < 4; ++qp) {
        red[(q0 + 2 * qp + 0) * RP + tx] = lo32(lsum2[qp]);
        red[(q0 + 2 * qp + 1) * RP + tx] = hi32(lsum2[qp]);
    }
    __syncthreads();

#pragma unroll
    for (int qp = 0; qp < 4; ++qp) {
#pragma unroll
        for (int s = 0; s < 2; ++s) {
            int row = q0 + 2 * qp + s;
            const float* rr = &red[row * RP];
            float l = rr[0];
#pragma unroll
            for (int t = 1; t < 16; ++t) l += rr[t];
            float inv = 1.0f / l;
            float4 o;
            if (s == 0) {
                o.x = lo32(o2[qp][0]) * inv; o.y = lo32(o2[qp][1]) * inv;
                o.z = lo32(o2[qp][2]) * inv; o.w = lo32(o2[qp][3]) * inv;
            } else {
                o.x = hi32(o2[qp][0]) * inv; o.y = hi32(o2[qp][1]) * inv;
                o.z = hi32(o2[qp][2]) * inv; o.w = hi32(o2[qp][3]) * inv;
            }
            size_t off = ((size_t)(b * SEQ + n0 + row) * NH + h) * DH + c0;
            *(float4*)&g_att[off] = o;
        }
    }
}

// =====================================================================
// host launcher
// =====================================================================
extern "C" void kernel_launch(void* const* d_in, const int* in_sizes, int n_in,
                              void* d_out, int out_size)
{
    const float *x = 0, *pos = 0, *qkv_w = 0, *proj_w = 0, *proj_b = 0;
    const float *qn_w = 0, *kn_w = 0;
    for (int i = 0; i < n_in; ++i) {
        int s = in_sizes[i];
        const float* p = (const float*)d_in[i];
        if      (s == BATCH * SEQ * DIM)  x = p;
        else if (s == BATCH * SEQ * 3)    pos = p;
        else if (s == 3 * DIM * DIM)      qkv_w = p;
        else if (s == DIM * DIM)          proj_w = p;
        else if (s == DIM)                proj_b = p;
        else if (s == DH) { if (!qn_w) qn_w = p; else kn_w = p; }
    }
    float* out = (float*)d_out;

    float *qkv, *att;
    cudaGetSymbolAddress((void**)&qkv, g_qkv);
    cudaGetSymbolAddress((void**)&att, g_att);

    const int smem_attn = (64 * QP + 4 * 64 * KP + 64 * SSP) * (int)sizeof(float); // 137216
    cudaFuncSetAttribute(attn4_kernel, cudaFuncAttributeMaxDynamicSharedMemorySize,
                         smem_attn);

    // 1) qkv = x @ qkv_w^T
    gemm_nt_kernel<<<dim3(3 * DIM / GBN, BATCH * SEQ / GBM), 256>>>(
        x, qkv_w, nullptr, qkv, BATCH * SEQ, 3 * DIM, DIM);

    // 2) rmsnorm + rope + split
    {
        int totalWarps = BATCH * SEQ * NH;
        int threads = 256;
        int blocks = (totalWarps * 32 + threads - 1) / threads;
        norm_rope_warp<<<blocks, threads>>>(pos, qn_w, kn_w);
    }

    // 3) flash attention v4
    attn4_kernel<<<dim3(SEQ / 128, BATCH * NH), 256, smem_attn>>>();

    // 4) out = att @ proj_w^T + proj_b
    gemm_nt_kernel<<<dim3(DIM / GBN, BATCH * SEQ / GBM), 256>>>(
        att, proj_w, proj_b, out, BATCH * SEQ, DIM, DIM);
}

// round 13
// speedup vs baseline: 3.6892x; 1.3663x over previous
#include <cuda_runtime.h>
#include <cuda_bf16.h>
#include <math.h>
#include <stdint.h>

// Problem constants
#define BATCH 2
#define SEQ   2048
#define DIM   768
#define NH    12
#define DH    64
#define ROPE_DIM 60
#define HALF  10
#define NT    (SEQ / 64)   // 32 key tiles of 64

// ---------------- scratch (static device arrays; no allocation) -------------
__device__ float g_qkv[BATCH * SEQ * 3 * DIM];
__device__ float g_q[BATCH * NH * SEQ * DH];
__device__ float g_k[BATCH * NH * SEQ * DH];
__device__ float g_v[BATCH * NH * SEQ * DH];
__device__ float g_att[BATCH * SEQ * DIM];

// ---------------- f32x2 packed helpers --------------------------------------
__device__ __forceinline__ unsigned long long pk2(float x) {
    unsigned long long r;
    asm("mov.b64 %0, {%1, %1};" : "=l"(r) : "r"(__float_as_uint(x)));
    return r;
}
__device__ __forceinline__ unsigned long long pack2(float lo, float hi) {
    unsigned long long r;
    asm("mov.b64 %0, {%1, %2};" : "=l"(r) : "r"(__float_as_uint(lo)), "r"(__float_as_uint(hi)));
    return r;
}
__device__ __forceinline__ void fma2(unsigned long long &d,
                                     unsigned long long a, unsigned long long b) {
    asm("fma.rn.f32x2 %0, %1, %2, %3;" : "=l"(d) : "l"(a), "l"(b), "l"(d));
}
__device__ __forceinline__ void add2(unsigned long long &d, unsigned long long a) {
    asm("add.rn.f32x2 %0, %1, %2;" : "=l"(d) : "l"(d), "l"(a));
}
__device__ __forceinline__ float lo32(unsigned long long v) {
    return __uint_as_float((unsigned)(v & 0xffffffffULL));
}
__device__ __forceinline__ float hi32(unsigned long long v) {
    return __uint_as_float((unsigned)(v >> 32));
}

// ---------------- cp.async helpers ------------------------------------------
__device__ __forceinline__ void cp_async16(void* smem_dst, const void* gmem_src) {
    unsigned s = (unsigned)__cvta_generic_to_shared(smem_dst);
    asm volatile("cp.async.cg.shared.global [%0], [%1], 16;" :: "r"(s), "l"(gmem_src));
}
__device__ __forceinline__ void cp_commit() {
    asm volatile("cp.async.commit_group;");
}
template<int N>
__device__ __forceinline__ void cp_wait() {
    asm volatile("cp.async.wait_group %0;" :: "n"(N));
}

// ---------------- mma.sync tf32 helpers (sm_80+, valid on plain sm_100) -----
__device__ __forceinline__ uint32_t f2tf32(float x) {
    uint32_t r;
    asm("cvt.rna.tf32.f32 %0, %1;" : "=r"(r) : "f"(x));
    return r;
}
__device__ __forceinline__ void mma_tf32(float* d, const uint32_t* a, const uint32_t* b) {
    asm volatile(
        "mma.sync.aligned.m16n8k8.row.col.f32.tf32.tf32.f32 "
        "{%0,%1,%2,%3}, {%4,%5,%6,%7}, {%8,%9}, {%0,%1,%2,%3};"
        : "+f"(d[0]), "+f"(d[1]), "+f"(d[2]), "+f"(d[3])
        : "r"(a[0]), "r"(a[1]), "r"(a[2]), "r"(a[3]), "r"(b[0]), "r"(b[1]));
}

// =====================================================================
// GEMM via mma.sync tf32: C[M][Nn] = A[M][K]*B[Nn][K]^T (+bias), fp32 IO.
// 128x128x32 tiles, 256 thr (8 warps, 2x4 grid, 64x32/warp = 4x4 frags).
// Smem natural [row][k] stride 36 (conflict-free fragment LDS),
// cp.async double-buffered, 1 sync/tile. cvt.rna.tf32 at fragment load.
// =====================================================================
#define BMM 128
#define BNN 128
#define BKK 32
#define ASTR 36                        // floats; row = 144 B (16B aligned)
#define GT_BUF (2 * BMM * ASTR)        // A+B floats per stage = 9216
#define GT_SMEM (2 * GT_BUF * 4)       // 73728 B

__global__ __launch_bounds__(256)
void gemm_mma_kernel(const float* __restrict__ A, const float* __restrict__ Bw,
                     const float* __restrict__ bias, float* __restrict__ C,
                     int M, int Nn, int K)
{
    extern __shared__ float smg[];
    const int tid = threadIdx.x;
    const int lane = tid & 31, wid = tid >> 5;
    const int wr = wid >> 2, wc = wid & 3;     // warp row (0..1) / col (0..3)
    const int gid = lane >> 2, tg = lane & 3;  // groupID / threadID_in_group
    const int mBase = blockIdx.y * BMM;
    const int nBase = blockIdx.x * BNN;
    const int nTiles = K / BKK;                // 24 for K=768

    float d[4][4][4];
#pragma unroll
    for (int mf = 0; mf < 4; ++mf)
#pragma unroll
        for (int nf = 0; nf < 4; ++nf)
#pragma unroll
            for (int e = 0; e < 4; ++e) d[mf][nf][e] = 0.f;

    // tile loader: 2048 16B chunks (A rows then B rows), 8 per thread
    auto load_tile = [&](int t, int buf) {
        const float* At = A + (size_t)mBase * K + t * BKK;
        const float* Bt = Bw + (size_t)nBase * K + t * BKK;
        float* as = smg + buf * GT_BUF;
        float* bs = as + BMM * ASTR;
#pragma unroll
        for (int e = 0; e < 8; ++e) {
            int idx = tid + e * 256;            // 0..2047
            int r = (idx >> 3) & 127;
            int c = idx & 7;                    // 16B chunk within 128B row
            if (idx < 1024)
                cp_async16(&as[r * ASTR + c * 4], &At[(size_t)r * K + c * 4]);
            else
                cp_async16(&bs[r * ASTR + c * 4], &Bt[(size_t)r * K + c * 4]);
        }
        cp_commit();
    };

    load_tile(0, 0);
    cp_wait<0>();
    __syncthreads();

    for (int t = 0; t < nTiles; ++t) {
        int cur = t & 1;
        if (t + 1 < nTiles) load_tile(t + 1, cur ^ 1);

        const float* as = smg + cur * GT_BUF;
        const float* bs = as + BMM * ASTR;

#pragma unroll
        for (int ks = 0; ks < BKK / 8; ++ks) {
            int k0 = ks * 8;
            uint32_t af[4][4];
#pragma unroll
            for (int mf = 0; mf < 4; ++mf) {
                int mr = wr * 64 + mf * 16 + gid;
                af[mf][0] = f2tf32(as[mr * ASTR + k0 + tg]);
                af[mf][1] = f2tf32(as[(mr + 8) * ASTR + k0 + tg]);
                af[mf][2] = f2tf32(as[mr * ASTR + k0 + tg + 4]);
                af[mf][3] = f2tf32(as[(mr + 8) * ASTR + k0 + tg + 4]);
            }
            uint32_t bf[4][2];
#pragma unroll
            for (int nf = 0; nf < 4; ++nf) {
                int nc = wc * 32 + nf * 8 + gid;
                bf[nf][0] = f2tf32(bs[nc * ASTR + k0 + tg]);
                bf[nf][1] = f2tf32(bs[nc * ASTR + k0 + tg + 4]);
            }
#pragma unroll
            for (int mf = 0; mf < 4; ++mf)
#pragma unroll
                for (int nf = 0; nf < 4; ++nf)
                    mma_tf32(d[mf][nf], af[mf], bf[nf]);
        }

        if (t + 1 < nTiles) cp_wait<0>();
        __syncthreads();        // next tile resident; cur free for t+2 load
    }

    // epilogue: c0/c1 at (row, 2tg), c2/c3 at (row+8, 2tg)
#pragma unroll
    for (int mf = 0; mf < 4; ++mf) {
#pragma unroll
        for (int nf = 0; nf < 4; ++nf) {
            int row = mBase + wr * 64 + mf * 16 + gid;
            int col = nBase + wc * 32 + nf * 8 + 2 * tg;
            float b0 = bias ? bias[col]     : 0.f;
            float b1 = bias ? bias[col + 1] : 0.f;
            float2 v0 = {d[mf][nf][0] + b0, d[mf][nf][1] + b1};
            float2 v1 = {d[mf][nf][2] + b0, d[mf][nf][3] + b1};
            *(float2*)&C[(size_t)row * Nn + col] = v0;
            *(float2*)&C[(size_t)(row + 8) * Nn + col] = v1;
        }
    }
}

// =====================================================================
// Warp-parallel rmsnorm + rope + split (unchanged, certified R8/R9).
// =====================================================================
__global__ void norm_rope_warp(const float* __restrict__ pos,
                               const float* __restrict__ qn_w,
                               const float* __restrict__ kn_w)
{
    int gw = (blockIdx.x * blockDim.x + threadIdx.x) >> 5;
    int t  = threadIdx.x & 31;
    if (gw >= BATCH * SEQ * NH) return;
    int h   = gw % NH;
    int tok = gw / NH;
    int b = tok / SEQ, n = tok % SEQ;

    const size_t base = (size_t)tok * (3 * DIM) + h * DH + 2 * t;
    float2 qv = *(const float2*)&g_qkv[base];
    float2 kv = *(const float2*)&g_qkv[base + DIM];
    float2 vv = *(const float2*)&g_qkv[base + 2 * DIM];

    float sq = qv.x * qv.x + qv.y * qv.y;
    float sk = kv.x * kv.x + kv.y * kv.y;
#pragma unroll
    for (int o = 16; o; o >>= 1) {
        sq += __shfl_xor_sync(0xffffffffu, sq, o);
        sk += __shfl_xor_sync(0xffffffffu, sk, o);
    }
    float rq = rsqrtf(sq * (1.0f / DH) + 1e-6f);
    float rk = rsqrtf(sk * (1.0f / DH) + 1e-6f);
    qv.x *= rq * qn_w[2 * t]; qv.y *= rq * qn_w[2 * t + 1];
    kv.x *= rk * kn_w[2 * t]; kv.y *= rk * kn_w[2 * t + 1];

    if (t < ROPE_DIM / 2) {
        int axis = t / HALF;
        int j = t - axis * HALF;
        float freq = powf(10000.0f, -(float)j / (float)HALF);
        float ang = pos[(size_t)tok * 3 + axis] * freq;
        float c = cosf(ang), s = sinf(ang);
        float qe = qv.x * c - qv.y * s, qo = qv.x * s + qv.y * c;
        qv.x = qe; qv.y = qo;
        float ke = kv.x * c - kv.y * s, ko = kv.x * s + kv.y * c;
        kv.x = ke; kv.y = ko;
    }

    const size_t ob = ((size_t)(b * NH + h) * SEQ + n) * DH + 2 * t;
    *(float2*)&g_q[ob] = qv;
    *(float2*)&g_k[ob] = kv;
    *(float2*)&g_v[ob] = vv;
}

// =====================================================================
// Flash attention v4 (unchanged, certified R9): q-tile 128, k-tile 64,
// 8q x 4k fragments with q-pair f32x2 packing, no-max softmax.
// =====================================================================
#define QP  132
#define KP  68
#define SSP 132
#define RP  17

__global__ __launch_bounds__(256)
void attn4_kernel()
{
    extern __shared__ float sm[];
    float* Qt  = sm;
    float* Kt0 = Qt  + 64 * QP;
    float* Kt1 = Kt0 + 64 * KP;
    float* Vs0 = Kt1 + 64 * KP;
    float* Vs1 = Vs0 + 64 * KP;
    float* Ss  = Vs1 + 64 * KP;

    const int tid = threadIdx.x;
    const int tx = tid & 15, ty = tid >> 4;
    const int q0 = ty * 8;
    const int c0 = tx * 4;
    const int bh = blockIdx.y;
    const int b  = bh / NH, h = bh % NH;
    const int n0 = blockIdx.x * 128;

    const float* Qg = g_q + ((size_t)bh * SEQ + n0) * DH;
    const float* Kg = g_k + (size_t)bh * SEQ * DH;
    const float* Vg = g_v + (size_t)bh * SEQ * DH;

    {
        const int lr = tid & 127;
        const int d0b = (tid >> 7) * 32;
#pragma unroll
        for (int e = 0; e < 8; ++e) {
            float4 qv = *(const float4*)&Qg[(size_t)lr * DH + d0b + e * 4];
            Qt[(d0b + e * 4 + 0) * QP + lr] = qv.x;
            Qt[(d0b + e * 4 + 1) * QP + lr] = qv.y;
            Qt[(d0b + e * 4 + 2) * QP + lr] = qv.z;
            Qt[(d0b + e * 4 + 3) * QP + lr] = qv.w;
        }
    }

    const int lrk = tid & 63;
    const int ldk = tid >> 6;

#pragma unroll
    for (int e = 0; e < 16; ++e)
        Kt0[(ldk + e * 4) * KP + lrk] = Kg[(size_t)lrk * DH + ldk + e * 4];
#pragma unroll
    for (int e = 0; e < 4; ++e) {
        int fidx = tid + e * 256;
        int r = fidx >> 4, dq = (fidx & 15) * 4;
        cp_async16(&Vs0[r * KP + dq], &Vg[(size_t)r * DH + dq]);
    }
    cp_commit();
    cp_wait<0>();
    __syncthreads();

    unsigned long long o2[4][4];
    unsigned long long lsum2[4];
#pragma unroll
    for (int qp = 0; qp < 4; ++qp) {
        lsum2[qp] = 0ULL;
#pragma unroll
        for (int j = 0; j < 4; ++j) o2[qp][j] = 0ULL;
    }

    for (int kt = 0; kt < NT; ++kt) {
        float* Ktc = (kt & 1) ? Kt1 : Kt0;
        float* Vsc = (kt & 1) ? Vs1 : Vs0;
        float* Ktn = (kt & 1) ? Kt0 : Kt1;
        float* Vsn = (kt & 1) ? Vs0 : Vs1;

        float kreg[16];
        if (kt + 1 < NT) {
            const float* Kgn = Kg + (size_t)(kt + 1) * 64 * DH;
            const float* Vgn = Vg + (size_t)(kt + 1) * 64 * DH;
#pragma unroll
            for (int e = 0; e < 4; ++e) {
                int fidx = tid + e * 256;
                int r = fidx >> 4, dq = (fidx & 15) * 4;
                cp_async16(&Vsn[r * KP + dq], &Vgn[(size_t)r * DH + dq]);
            }
            cp_commit();
#pragma unroll
            for (int e = 0; e < 16; ++e)
                kreg[e] = Kgn[(size_t)lrk * DH + ldk + e * 4];
        }

        unsigned long long s2[4][4];
#pragma unroll
        for (int qp = 0; qp < 4; ++qp)
#pragma unroll
            for (int j = 0; j < 4; ++j) s2[qp][j] = 0ULL;

#pragma unroll 8
        for (int d = 0; d < 64; ++d) {
            ulonglong2 a01 = *(const ulonglong2*)&Qt[d * QP + q0];
            ulonglong2 a23 = *(const ulonglong2*)&Qt[d * QP + q0 + 4];
            float4 bv = *(const float4*)&Ktc[d * KP + c0];
            unsigned long long b2[4] = {pk2(bv.x), pk2(bv.y), pk2(bv.z), pk2(bv.w)};
            unsigned long long a2[4] = {a01.x, a01.y, a23.x, a23.y};
#pragma unroll
            for (int qp = 0; qp < 4; ++qp)
#pragma unroll
                for (int j = 0; j < 4; ++j) fma2(s2[qp][j], a2[qp], b2[j]);
        }

#pragma unroll
        for (int qp = 0; qp < 4; ++qp)
#pragma unroll
            for (int j = 0; j < 4; ++j) {
                float plo = __expf(lo32(s2[qp][j]) * 0.125f);
                float phi = __expf(hi32(s2[qp][j]) * 0.125f);
                unsigned long long p2 = pack2(plo, phi);
                *(unsigned long long*)&Ss[(c0 + j) * SSP + q0 + 2 * qp] = p2;
                add2(lsum2[qp], p2);
            }
        __syncthreads();

#pragma unroll 4
        for (int kk = 0; kk < 64; ++kk) {
            ulonglong2 pA = *(const ulonglong2*)&Ss[kk * SSP + q0];
            ulonglong2 pB = *(const ulonglong2*)&Ss[kk * SSP + q0 + 4];
            float4 vv = *(const float4*)&Vsc[kk * KP + c0];
            unsigned long long v2[4] = {pk2(vv.x), pk2(vv.y), pk2(vv.z), pk2(vv.w)};
            unsigned long long p2v[4] = {pA.x, pA.y, pB.x, pB.y};
#pragma unroll
            for (int qp = 0; qp < 4; ++qp)
#pragma unroll
                for (int j = 0; j < 4; ++j) fma2(o2[qp][j], p2v[qp], v2[j]);
        }

        if (kt + 1 < NT) {
#pragma unroll
            for (int e = 0; e < 16; ++e)
                Ktn[(ldk + e * 4) * KP + lrk] = kreg[e];
        }

        cp_wait<0>();
        __syncthreads();
    }

    float* red = Kt0;
#pragma unroll
    for (int qp = 0; qp < 4; ++qp) {
        red[(q0 + 2 * qp + 0) * RP + tx] = lo32(lsum2[qp]);
        red[(q0 + 2 * qp + 1) * RP + tx] = hi32(lsum2[qp]);
    }
    __syncthreads();

#pragma unroll
    for (int qp = 0; qp < 4; ++qp) {
#pragma unroll
        for (int s = 0; s < 2; ++s) {
            int row = q0 + 2 * qp + s;
            const float* rr = &red[row * RP];
            float l = rr[0];
#pragma unroll
            for (int t = 1; t < 16; ++t) l += rr[t];
            float inv = 1.0f / l;
            float4 o;
            if (s == 0) {
                o.x = lo32(o2[qp][0]) * inv; o.y = lo32(o2[qp][1]) * inv;
                o.z = lo32(o2[qp][2]) * inv; o.w = lo32(o2[qp][3]) * inv;
            } else {
                o.x = hi32(o2[qp][0]) * inv; o.y = hi32(o2[qp][1]) * inv;
                o.z = hi32(o2[qp][2]) * inv; o.w = hi32(o2[qp][3]) * inv;
            }
            size_t off = ((size_t)(b * SEQ + n0 + row) * NH + h) * DH + c0;
            *(float4*)&g_att[off] = o;
        }
    }
}

// =====================================================================
// host launcher
// =====================================================================
extern "C" void kernel_launch(void* const* d_in, const int* in_sizes, int n_in,
                              void* d_out, int out_size)
{
    const float *x = 0, *pos = 0, *qkv_w = 0, *proj_w = 0, *proj_b = 0;
    const float *qn_w = 0, *kn_w = 0;
    for (int i = 0; i < n_in; ++i) {
        int s = in_sizes[i];
        const float* p = (const float*)d_in[i];
        if      (s == BATCH * SEQ * DIM)  x = p;
        else if (s == BATCH * SEQ * 3)    pos = p;
        else if (s == 3 * DIM * DIM)      qkv_w = p;
        else if (s == DIM * DIM)          proj_w = p;
        else if (s == DIM)                proj_b = p;
        else if (s == DH) { if (!qn_w) qn_w = p; else kn_w = p; }
    }
    float* out = (float*)d_out;

    float *qkv, *att;
    cudaGetSymbolAddress((void**)&qkv, g_qkv);
    cudaGetSymbolAddress((void**)&att, g_att);

    cudaFuncSetAttribute(gemm_mma_kernel, cudaFuncAttributeMaxDynamicSharedMemorySize,
                         GT_SMEM);
    const int smem_attn = (64 * QP + 4 * 64 * KP + 64 * SSP) * (int)sizeof(float);
    cudaFuncSetAttribute(attn4_kernel, cudaFuncAttributeMaxDynamicSharedMemorySize,
                         smem_attn);

    // 1) qkv = x @ qkv_w^T  (tf32 mma.sync tensor cores)
    gemm_mma_kernel<<<dim3(3 * DIM / BNN, BATCH * SEQ / BMM), 256, GT_SMEM>>>(
        x, qkv_w, nullptr, qkv, BATCH * SEQ, 3 * DIM, DIM);

    // 2) rmsnorm + rope + split
    {
        int totalWarps = BATCH * SEQ * NH;
        int threads = 256;
        int blocks = (totalWarps * 32 + threads - 1) / threads;
        norm_rope_warp<<<blocks, threads>>>(pos, qn_w, kn_w);
    }

    // 3) flash attention v4 (fp32)
    attn4_kernel<<<dim3(SEQ / 128, BATCH * NH), 256, smem_attn>>>();

    // 4) out = att @ proj_w^T + proj_b  (tf32 mma.sync tensor cores)
    gemm_mma_kernel<<<dim3(DIM / BNN, BATCH * SEQ / BMM), 256, GT_SMEM>>>(
        att, proj_w, proj_b, out, BATCH * SEQ, DIM, DIM);
}

// round 14
// speedup vs baseline: 5.6278x; 1.5255x over previous
#include <cuda_runtime.h>
#include <cuda_bf16.h>
#include <math.h>
#include <stdint.h>

// Problem constants
#define BATCH 2
#define SEQ   2048
#define DIM   768
#define NH    12
#define DH    64
#define ROPE_DIM 60
#define HALF  10
#define NT    (SEQ / 64)   // 32 key tiles of 64

// ---------------- scratch (static device arrays; no allocation) -------------
__device__ float g_qkv[BATCH * SEQ * 3 * DIM];
__device__ float g_q[BATCH * NH * SEQ * DH];
__device__ float g_k[BATCH * NH * SEQ * DH];
__device__ float g_v[BATCH * NH * SEQ * DH];
__device__ float g_att[BATCH * SEQ * DIM];

// ---------------- cp.async helpers ------------------------------------------
__device__ __forceinline__ void cp_async16(void* smem_dst, const void* gmem_src) {
    unsigned s = (unsigned)__cvta_generic_to_shared(smem_dst);
    asm volatile("cp.async.cg.shared.global [%0], [%1], 16;" :: "r"(s), "l"(gmem_src));
}
__device__ __forceinline__ void cp_commit() {
    asm volatile("cp.async.commit_group;");
}
template<int N>
__device__ __forceinline__ void cp_wait() {
    asm volatile("cp.async.wait_group %0;" :: "n"(N));
}

// ---------------- mma.sync tf32 helpers (sm_80+, valid on plain sm_100) -----
__device__ __forceinline__ uint32_t f2tf32(float x) {
    uint32_t r;
    asm("cvt.rna.tf32.f32 %0, %1;" : "=r"(r) : "f"(x));
    return r;
}
__device__ __forceinline__ void mma_tf32(float* d, const uint32_t* a, const uint32_t* b) {
    asm volatile(
        "mma.sync.aligned.m16n8k8.row.col.f32.tf32.tf32.f32 "
        "{%0,%1,%2,%3}, {%4,%5,%6,%7}, {%8,%9}, {%0,%1,%2,%3};"
        : "+f"(d[0]), "+f"(d[1]), "+f"(d[2]), "+f"(d[3])
        : "r"(a[0]), "r"(a[1]), "r"(a[2]), "r"(a[3]), "r"(b[0]), "r"(b[1]));
}

// =====================================================================
// GEMM via mma.sync tf32 (unchanged — certified R13).
// =====================================================================
#define BMM 128
#define BNN 128
#define BKK 32
#define ASTR 36
#define GT_BUF (2 * BMM * ASTR)
#define GT_SMEM (2 * GT_BUF * 4)

__global__ __launch_bounds__(256)
void gemm_mma_kernel(const float* __restrict__ A, const float* __restrict__ Bw,
                     const float* __restrict__ bias, float* __restrict__ C,
                     int M, int Nn, int K)
{
    extern __shared__ float smg[];
    const int tid = threadIdx.x;
    const int lane = tid & 31, wid = tid >> 5;
    const int wr = wid >> 2, wc = wid & 3;
    const int gid = lane >> 2, tg = lane & 3;
    const int mBase = blockIdx.y * BMM;
    const int nBase = blockIdx.x * BNN;
    const int nTiles = K / BKK;

    float d[4][4][4];
#pragma unroll
    for (int mf = 0; mf < 4; ++mf)
#pragma unroll
        for (int nf = 0; nf < 4; ++nf)
#pragma unroll
            for (int e = 0; e < 4; ++e) d[mf][nf][e] = 0.f;

    auto load_tile = [&](int t, int buf) {
        const float* At = A + (size_t)mBase * K + t * BKK;
        const float* Bt = Bw + (size_t)nBase * K + t * BKK;
        float* as = smg + buf * GT_BUF;
        float* bs = as + BMM * ASTR;
#pragma unroll
        for (int e = 0; e < 8; ++e) {
            int idx = tid + e * 256;
            int r = (idx >> 3) & 127;
            int c = idx & 7;
            if (idx < 1024)
                cp_async16(&as[r * ASTR + c * 4], &At[(size_t)r * K + c * 4]);
            else
                cp_async16(&bs[r * ASTR + c * 4], &Bt[(size_t)r * K + c * 4]);
        }
        cp_commit();
    };

    load_tile(0, 0);
    cp_wait<0>();
    __syncthreads();

    for (int t = 0; t < nTiles; ++t) {
        int cur = t & 1;
        if (t + 1 < nTiles) load_tile(t + 1, cur ^ 1);

        const float* as = smg + cur * GT_BUF;
        const float* bs = as + BMM * ASTR;

#pragma unroll
        for (int ks = 0; ks < BKK / 8; ++ks) {
            int k0 = ks * 8;
            uint32_t af[4][4];
#pragma unroll
            for (int mf = 0; mf < 4; ++mf) {
                int mr = wr * 64 + mf * 16 + gid;
                af[mf][0] = f2tf32(as[mr * ASTR + k0 + tg]);
                af[mf][1] = f2tf32(as[(mr + 8) * ASTR + k0 + tg]);
                af[mf][2] = f2tf32(as[mr * ASTR + k0 + tg + 4]);
                af[mf][3] = f2tf32(as[(mr + 8) * ASTR + k0 + tg + 4]);
            }
            uint32_t bf[4][2];
#pragma unroll
            for (int nf = 0; nf < 4; ++nf) {
                int nc = wc * 32 + nf * 8 + gid;
                bf[nf][0] = f2tf32(bs[nc * ASTR + k0 + tg]);
                bf[nf][1] = f2tf32(bs[nc * ASTR + k0 + tg + 4]);
            }
#pragma unroll
            for (int mf = 0; mf < 4; ++mf)
#pragma unroll
                for (int nf = 0; nf < 4; ++nf)
                    mma_tf32(d[mf][nf], af[mf], bf[nf]);
        }

        if (t + 1 < nTiles) cp_wait<0>();
        __syncthreads();
    }

#pragma unroll
    for (int mf = 0; mf < 4; ++mf) {
#pragma unroll
        for (int nf = 0; nf < 4; ++nf) {
            int row = mBase + wr * 64 + mf * 16 + gid;
            int col = nBase + wc * 32 + nf * 8 + 2 * tg;
            float b0 = bias ? bias[col]     : 0.f;
            float b1 = bias ? bias[col + 1] : 0.f;
            float2 v0 = {d[mf][nf][0] + b0, d[mf][nf][1] + b1};
            float2 v1 = {d[mf][nf][2] + b0, d[mf][nf][3] + b1};
            *(float2*)&C[(size_t)row * Nn + col] = v0;
            *(float2*)&C[(size_t)(row + 8) * Nn + col] = v1;
        }
    }
}

// =====================================================================
// Warp-parallel rmsnorm + rope + split (unchanged — certified R8/R9).
// =====================================================================
__global__ void norm_rope_warp(const float* __restrict__ pos,
                               const float* __restrict__ qn_w,
                               const float* __restrict__ kn_w)
{
    int gw = (blockIdx.x * blockDim.x + threadIdx.x) >> 5;
    int t  = threadIdx.x & 31;
    if (gw >= BATCH * SEQ * NH) return;
    int h   = gw % NH;
    int tok = gw / NH;
    int b = tok / SEQ, n = tok % SEQ;

    const size_t base = (size_t)tok * (3 * DIM) + h * DH + 2 * t;
    float2 qv = *(const float2*)&g_qkv[base];
    float2 kv = *(const float2*)&g_qkv[base + DIM];
    float2 vv = *(const float2*)&g_qkv[base + 2 * DIM];

    float sq = qv.x * qv.x + qv.y * qv.y;
    float sk = kv.x * kv.x + kv.y * kv.y;
#pragma unroll
    for (int o = 16; o; o >>= 1) {
        sq += __shfl_xor_sync(0xffffffffu, sq, o);
        sk += __shfl_xor_sync(0xffffffffu, sk, o);
    }
    float rq = rsqrtf(sq * (1.0f / DH) + 1e-6f);
    float rk = rsqrtf(sk * (1.0f / DH) + 1e-6f);
    qv.x *= rq * qn_w[2 * t]; qv.y *= rq * qn_w[2 * t + 1];
    kv.x *= rk * kn_w[2 * t]; kv.y *= rk * kn_w[2 * t + 1];

    if (t < ROPE_DIM / 2) {
        int axis = t / HALF;
        int j = t - axis * HALF;
        float freq = powf(10000.0f, -(float)j / (float)HALF);
        float ang = pos[(size_t)tok * 3 + axis] * freq;
        float c = cosf(ang), s = sinf(ang);
        float qe = qv.x * c - qv.y * s, qo = qv.x * s + qv.y * c;
        qv.x = qe; qv.y = qo;
        float ke = kv.x * c - kv.y * s, ko = kv.x * s + kv.y * c;
        kv.x = ke; kv.y = ko;
    }

    const size_t ob = ((size_t)(b * NH + h) * SEQ + n) * DH + 2 * t;
    *(float2*)&g_q[ob] = qv;
    *(float2*)&g_k[ob] = kv;
    *(float2*)&g_v[ob] = vv;
}

// =====================================================================
// Flash attention v5: tf32 mma.sync for S = QK^T and O = PV.
// q-tile 128, k-tile 64. 8 warps in 2x4 grid:
//   S: warp (wr,wc) -> rows [wr*64,+64) x kcols [wc*16,+16)
//   O: warp (wr,wc) -> rows [wr*64,+64) x dcols [wc*16,+16)
// No-max softmax (|S|<=8); P RNA-rounded to tf32 BEFORE both the row-sum
// and the smem store (normalization consistent with MMA weights).
// Smem (stride 68 = 4 mod 32 -> conflict-free fragment LDS):
//   Qs [128 q][68] tf32 bits (pre-converted once)
//   Ks0/Ks1 [64 k][68] fp32 (cp.async; convert at fragment load)
//   Vt0/Vt1 [64 d][68] tf32 bits (transposed scalar staging, certified R9 style)
//   Ss [128 q][68] tf32 bits (P round-trip)
// Pipeline: certified attn4 scheme (prefetch after syncA, stage after PV).
// =====================================================================
#define SST 68
#define A5_SMEM (512 * SST * 4)     // (128+64*2+64*2+128) rows = 139264 B
#define RPX 17

__global__ __launch_bounds__(256)
void attn5_kernel()
{
    extern __shared__ float sm[];
    float* Qs  = sm;                  // [128][SST] tf32 bits
    float* Ks0 = Qs  + 128 * SST;     // [64][SST]  fp32
    float* Ks1 = Ks0 + 64 * SST;
    float* Vt0 = Ks1 + 64 * SST;      // [64][SST]  tf32 bits (V^T)
    float* Vt1 = Vt0 + 64 * SST;
    float* Ss  = Vt1 + 64 * SST;      // [128][SST] tf32 bits (P)

    const int tid = threadIdx.x;
    const int lane = tid & 31, wid = tid >> 5;
    const int wr = wid >> 2, wc = wid & 3;
    const int gid = lane >> 2, tg = lane & 3;
    const int bh = blockIdx.y;
    const int b  = bh / NH, h = bh % NH;
    const int n0 = blockIdx.x * 128;

    const float* Qg = g_q + ((size_t)bh * SEQ + n0) * DH;
    const float* Kg = g_k + (size_t)bh * SEQ * DH;
    const float* Vg = g_v + (size_t)bh * SEQ * DH;

    // ---- Q tile: load, convert to tf32 bits, natural [q][d] ----
#pragma unroll
    for (int e = 0; e < 32; ++e) {
        int idx = tid + e * 256;          // 0..8191
        int q = idx >> 6, dd = idx & 63;
        Qs[q * SST + dd] = __uint_as_float(f2tf32(Qg[(size_t)q * DH + dd]));
    }

    // K cp.async mapping: 1024 16B chunks / 256 thr
    auto load_k = [&](const float* src, float* dst) {
#pragma unroll
        for (int e = 0; e < 4; ++e) {
            int fidx = tid + e * 256;
            int r = fidx >> 4, c4 = (fidx & 15) * 4;
            cp_async16(&dst[r * SST + c4], &src[(size_t)r * DH + c4]);
        }
        cp_commit();
    };
    // V transpose staging mapping (certified attn4 K-path style)
    const int lrv = tid & 63;             // k row
    const int ldv = tid >> 6;             // d base 0..3

    // ---- preload tile 0 ----
    load_k(Kg, Ks0);
#pragma unroll
    for (int e = 0; e < 16; ++e) {
        uint32_t v = f2tf32(Vg[(size_t)lrv * DH + ldv + e * 4]);
        Vt0[(ldv + e * 4) * SST + lrv] = __uint_as_float(v);
    }
    cp_wait<0>();
    __syncthreads();     // (A) for kt=0

    float o[4][2][4];
    float lsA[4], lsB[4];
#pragma unroll
    for (int mf = 0; mf < 4; ++mf) {
        lsA[mf] = 0.f; lsB[mf] = 0.f;
#pragma unroll
        for (int nf = 0; nf < 2; ++nf)
#pragma unroll
            for (int e = 0; e < 4; ++e) o[mf][nf][e] = 0.f;
    }

    for (int kt = 0; kt < NT; ++kt) {
        float* Ksc = (kt & 1) ? Ks1 : Ks0;
        float* Vtc = (kt & 1) ? Vt1 : Vt0;
        float* Ksn = (kt & 1) ? Ks0 : Ks1;
        float* Vtn = (kt & 1) ? Vt0 : Vt1;

        // ---- prefetch next tile (safe: past sync A) ----
        uint32_t vreg[16];
        if (kt + 1 < NT) {
            const float* Kgn = Kg + (size_t)(kt + 1) * 64 * DH;
            const float* Vgn = Vg + (size_t)(kt + 1) * 64 * DH;
            load_k(Kgn, Ksn);
#pragma unroll
            for (int e = 0; e < 16; ++e)
                vreg[e] = f2tf32(Vgn[(size_t)lrv * DH + ldv + e * 4]);
        }

        // ---- S = Q K^T (tf32 mma) ----
        float s[4][2][4];
#pragma unroll
        for (int mf = 0; mf < 4; ++mf)
#pragma unroll
            for (int nf = 0; nf < 2; ++nf)
#pragma unroll
                for (int e = 0; e < 4; ++e) s[mf][nf][e] = 0.f;

#pragma unroll
        for (int ds = 0; ds < 8; ++ds) {
            int d0 = ds * 8;
            uint32_t af[4][4];
#pragma unroll
            for (int mf = 0; mf < 4; ++mf) {
                int mr = wr * 64 + mf * 16 + gid;
                af[mf][0] = __float_as_uint(Qs[mr * SST + d0 + tg]);
                af[mf][1] = __float_as_uint(Qs[(mr + 8) * SST + d0 + tg]);
                af[mf][2] = __float_as_uint(Qs[mr * SST + d0 + tg + 4]);
                af[mf][3] = __float_as_uint(Qs[(mr + 8) * SST + d0 + tg + 4]);
            }
            uint32_t bf[2][2];
#pragma unroll
            for (int nf = 0; nf < 2; ++nf) {
                int kc = wc * 16 + nf * 8 + gid;
                bf[nf][0] = f2tf32(Ksc[kc * SST + d0 + tg]);
                bf[nf][1] = f2tf32(Ksc[kc * SST + d0 + tg + 4]);
            }
#pragma unroll
            for (int mf = 0; mf < 4; ++mf)
#pragma unroll
                for (int nf = 0; nf < 2; ++nf)
                    mma_tf32(s[mf][nf], af[mf], bf[nf]);
        }

        // ---- P = exp(S/8), RNA-round to tf32, sum rounded, store ----
#pragma unroll
        for (int mf = 0; mf < 4; ++mf) {
            int r0 = wr * 64 + mf * 16 + gid;
#pragma unroll
            for (int nf = 0; nf < 2; ++nf) {
                int col = wc * 16 + nf * 8 + 2 * tg;
                float p0 = __uint_as_float(f2tf32(__expf(s[mf][nf][0] * 0.125f)));
                float p1 = __uint_as_float(f2tf32(__expf(s[mf][nf][1] * 0.125f)));
                float p2 = __uint_as_float(f2tf32(__expf(s[mf][nf][2] * 0.125f)));
                float p3 = __uint_as_float(f2tf32(__expf(s[mf][nf][3] * 0.125f)));
                lsA[mf] += p0 + p1;
                lsB[mf] += p2 + p3;
                *(float2*)&Ss[r0 * SST + col] = make_float2(p0, p1);
                *(float2*)&Ss[(r0 + 8) * SST + col] = make_float2(p2, p3);
            }
        }
        __syncthreads();   // (B) P visible to all warps

        // ---- O += P V (tf32 mma; A=P from Ss, B=V^T from Vtc) ----
#pragma unroll
        for (int ks = 0; ks < 8; ++ks) {
            int kk0 = ks * 8;
            uint32_t af[4][4];
#pragma unroll
            for (int mf = 0; mf < 4; ++mf) {
                int mr = wr * 64 + mf * 16 + gid;
                af[mf][0] = __float_as_uint(Ss[mr * SST + kk0 + tg]);
                af[mf][1] = __float_as_uint(Ss[(mr + 8) * SST + kk0 + tg]);
                af[mf][2] = __float_as_uint(Ss[mr * SST + kk0 + tg + 4]);
                af[mf][3] = __float_as_uint(Ss[(mr + 8) * SST + kk0 + tg + 4]);
            }
            uint32_t bf[2][2];
#pragma unroll
            for (int nf = 0; nf < 2; ++nf) {
                int dc = wc * 16 + nf * 8 + gid;
                bf[nf][0] = __float_as_uint(Vtc[dc * SST + kk0 + tg]);
                bf[nf][1] = __float_as_uint(Vtc[dc * SST + kk0 + tg + 4]);
            }
#pragma unroll
            for (int mf = 0; mf < 4; ++mf)
#pragma unroll
                for (int nf = 0; nf < 2; ++nf)
                    mma_tf32(o[mf][nf], af[mf], bf[nf]);
        }

        // ---- stage next V^T -> other buffer (readers done pre-syncA) ----
        if (kt + 1 < NT) {
#pragma unroll
            for (int e = 0; e < 16; ++e)
                Vtn[(ldv + e * 4) * SST + lrv] = __uint_as_float(vreg[e]);
        }

        cp_wait<0>();
        __syncthreads();   // (A) next buffers ready; Ss free
    }

    // ---- final row-sum reduction (reuse Ks0 as scratch [128][RPX]) ----
    float* red = Ks0;
#pragma unroll
    for (int mf = 0; mf < 4; ++mf) {
        int r0 = wr * 64 + mf * 16 + gid;
        red[r0 * RPX + wc * 4 + tg] = lsA[mf];
        red[(r0 + 8) * RPX + wc * 4 + tg] = lsB[mf];
    }
    __syncthreads();

#pragma unroll
    for (int mf = 0; mf < 4; ++mf) {
        int r0 = wr * 64 + mf * 16 + gid;
        float lA = 0.f, lB = 0.f;
#pragma unroll
        for (int t = 0; t < 16; ++t) {
            lA += red[r0 * RPX + t];
            lB += red[(r0 + 8) * RPX + t];
        }
        float invA = 1.0f / lA, invB = 1.0f / lB;
#pragma unroll
        for (int nf = 0; nf < 2; ++nf) {
            int dcol = wc * 16 + nf * 8 + 2 * tg;
            size_t offA = ((size_t)(b * SEQ + n0 + r0) * NH + h) * DH + dcol;
            size_t offB = ((size_t)(b * SEQ + n0 + r0 + 8) * NH + h) * DH + dcol;
            *(float2*)&g_att[offA] = make_float2(o[mf][nf][0] * invA,
                                                 o[mf][nf][1] * invA);
            *(float2*)&g_att[offB] = make_float2(o[mf][nf][2] * invB,
                                                 o[mf][nf][3] * invB);
        }
    }
}

// =====================================================================
// host launcher
// =====================================================================
extern "C" void kernel_launch(void* const* d_in, const int* in_sizes, int n_in,
                              void* d_out, int out_size)
{
    const float *x = 0, *pos = 0, *qkv_w = 0, *proj_w = 0, *proj_b = 0;
    const float *qn_w = 0, *kn_w = 0;
    for (int i = 0; i < n_in; ++i) {
        int s = in_sizes[i];
        const float* p = (const float*)d_in[i];
        if      (s == BATCH * SEQ * DIM)  x = p;
        else if (s == BATCH * SEQ * 3)    pos = p;
        else if (s == 3 * DIM * DIM)      qkv_w = p;
        else if (s == DIM * DIM)          proj_w = p;
        else if (s == DIM)                proj_b = p;
        else if (s == DH) { if (!qn_w) qn_w = p; else kn_w = p; }
    }
    float* out = (float*)d_out;

    float *qkv, *att;
    cudaGetSymbolAddress((void**)&qkv, g_qkv);
    cudaGetSymbolAddress((void**)&att, g_att);

    cudaFuncSetAttribute(gemm_mma_kernel, cudaFuncAttributeMaxDynamicSharedMemorySize,
                         GT_SMEM);
    cudaFuncSetAttribute(attn5_kernel, cudaFuncAttributeMaxDynamicSharedMemorySize,
                         A5_SMEM);

    // 1) qkv = x @ qkv_w^T  (tf32 mma.sync)
    gemm_mma_kernel<<<dim3(3 * DIM / BNN, BATCH * SEQ / BMM), 256, GT_SMEM>>>(
        x, qkv_w, nullptr, qkv, BATCH * SEQ, 3 * DIM, DIM);

    // 2) rmsnorm + rope + split
    {
        int totalWarps = BATCH * SEQ * NH;
        int threads = 256;
        int blocks = (totalWarps * 32 + threads - 1) / threads;
        norm_rope_warp<<<blocks, threads>>>(pos, qn_w, kn_w);
    }

    // 3) flash attention v5 (tf32 mma.sync)
    attn5_kernel<<<dim3(SEQ / 128, BATCH * NH), 256, A5_SMEM>>>();

    // 4) out = att @ proj_w^T + proj_b  (tf32 mma.sync)
    gemm_mma_kernel<<<dim3(DIM / BNN, BATCH * SEQ / BMM), 256, GT_SMEM>>>(
        att, proj_w, proj_b, out, BATCH * SEQ, DIM, DIM);
}